// round 12
// baseline (speedup 1.0000x reference)
#include <cuda_runtime.h>
#include <cuda_bf16.h>
#include <stdint.h>

// Problem constants
#define NN 50000
#define EE 600000
#define FF 128
#define HH 128
#define OO 64
#define RR 8
#define NS 9                       // 8 relations + root slot
#define NB1 ((NN + 1023) / 1024)   // 49 scan blocks

// ---------------------------------------------------------------------------
// Device scratch
// ---------------------------------------------------------------------------
__device__ float          g_Y[(size_t)NN * NS * HH];  // 230.4 MB projection buf
__device__ __nv_bfloat16  g_Ah[(size_t)NN * FF];      // A hi plane
__device__ __nv_bfloat16  g_Al[(size_t)NN * FF];      // A lo plane
__device__ __nv_bfloat16  g_Wh[NS * FF * HH];         // W hi (slots 0..8)
__device__ __nv_bfloat16  g_Wl[NS * FF * HH];         // W lo
__device__ int            g_bcnt[NN];
__device__ int            g_bcur[NN];
__device__ int            g_boff[NN + 1];
__device__ int            g_part[64];
__device__ int2           g_emeta[EE];                // sorted: {src*9+r, coef}
__device__ unsigned       g_mm[2];
__device__ int            g_is64;

// ---------------------------------------------------------------------------
// Helpers
// ---------------------------------------------------------------------------
__device__ __forceinline__ int load_idx(const void* p, size_t i) {
    return g_is64 ? (int)((const long long*)p)[i] : ((const int*)p)[i];
}
__device__ __forceinline__ uint32_t smem_u32(const void* p) {
    uint32_t a;
    asm("{ .reg .u64 t; cvta.to.shared.u64 t, %1; cvt.u32.u64 %0, t; }"
        : "=r"(a) : "l"(p));
    return a;
}
__device__ __forceinline__ void cp16(uint32_t d, const void* s, uint32_t nbytes) {
    asm volatile("cp.async.cg.shared.global [%0], [%1], 16, %2;"
                 :: "r"(d), "l"(s), "r"(nbytes) : "memory");
}
__device__ __forceinline__ void ldsm_x4(uint32_t& r0, uint32_t& r1,
                                        uint32_t& r2, uint32_t& r3, uint32_t a) {
    asm volatile("ldmatrix.sync.aligned.m8n8.x4.shared.b16 {%0,%1,%2,%3}, [%4];"
                 : "=r"(r0), "=r"(r1), "=r"(r2), "=r"(r3) : "r"(a));
}
__device__ __forceinline__ void ldsm_x4t(uint32_t& r0, uint32_t& r1,
                                         uint32_t& r2, uint32_t& r3, uint32_t a) {
    asm volatile("ldmatrix.sync.aligned.m8n8.x4.trans.shared.b16 {%0,%1,%2,%3}, [%4];"
                 : "=r"(r0), "=r"(r1), "=r"(r2), "=r"(r3) : "r"(a));
}
__device__ __forceinline__ void mma_bf16(float* c, const uint32_t* a,
                                         uint32_t b0, uint32_t b1) {
    asm volatile(
        "mma.sync.aligned.m16n8k16.row.col.f32.bf16.bf16.f32 "
        "{%0,%1,%2,%3}, {%4,%5,%6,%7}, {%8,%9}, {%0,%1,%2,%3};"
        : "+f"(c[0]), "+f"(c[1]), "+f"(c[2]), "+f"(c[3])
        : "r"(a[0]), "r"(a[1]), "r"(a[2]), "r"(a[3]), "r"(b0), "r"(b1));
}
__device__ __forceinline__ void split1(float v, unsigned short& h, unsigned short& l) {
    __nv_bfloat16 b1 = __float2bfloat16(v);
    __nv_bfloat16 b2 = __float2bfloat16(v - __bfloat162float(b1));
    h = __bfloat16_as_ushort(b1);
    l = __bfloat16_as_ushort(b2);
}
__device__ __forceinline__ void split4_store(const float* vs,
                                             __nv_bfloat16* hi,
                                             __nv_bfloat16* lo, int i) {
    unsigned short h[4], l[4];
    #pragma unroll
    for (int j = 0; j < 4; j++) split1(vs[j], h[j], l[j]);
    uint2 ph, pl;
    ph.x = (uint32_t)h[0] | ((uint32_t)h[1] << 16);
    ph.y = (uint32_t)h[2] | ((uint32_t)h[3] << 16);
    pl.x = (uint32_t)l[0] | ((uint32_t)l[1] << 16);
    pl.y = (uint32_t)l[2] | ((uint32_t)l[3] << 16);
    ((uint2*)hi)[i] = ph;
    ((uint2*)lo)[i] = pl;
}

// ---------------------------------------------------------------------------
// Split fp32 -> bf16 hi/lo planes (x / h)
// ---------------------------------------------------------------------------
__global__ void k_split(const float* __restrict__ src,
                        __nv_bfloat16* __restrict__ hi,
                        __nv_bfloat16* __restrict__ lo, int n4) {
    int i = blockIdx.x * blockDim.x + threadIdx.x;
    if (i >= n4) return;
    float4 v = ((const float4*)src)[i];
    float vs[4] = {v.x, v.y, v.z, v.w};
    split4_store(vs, hi, lo, i);
}

// Two-source split: [W (n4a float4s)] then [root (n4b float4s)] into
// contiguous hi/lo planes.
__global__ void k_splitW(const float* __restrict__ srcA, int n4a,
                         const float* __restrict__ srcB, int n4b,
                         __nv_bfloat16* __restrict__ hi,
                         __nv_bfloat16* __restrict__ lo) {
    int i = blockIdx.x * blockDim.x + threadIdx.x;
    if (i >= n4a + n4b) return;
    float4 v = (i < n4a) ? ((const float4*)srcA)[i]
                         : ((const float4*)srcB)[i - n4a];
    float vs[4] = {v.x, v.y, v.z, v.w};
    split4_store(vs, hi, lo, i);
}

// ---------------------------------------------------------------------------
// Edge preprocessing
// ---------------------------------------------------------------------------
__global__ void k_zerodet(const void* ei) {
    int i = blockIdx.x * blockDim.x + threadIdx.x;
    for (int j = i; j < NN; j += gridDim.x * blockDim.x) { g_bcnt[j] = 0; g_bcur[j] = 0; }
    if (i == 0) {
        g_mm[0] = 0xFFFFFFFFu; g_mm[1] = 0u;
        const int* p = (const int*)ei;
        int nz = 0;
        for (int k = 1; k < 2001; k += 2) nz |= p[k];
        g_is64 = (nz == 0) ? 1 : 0;
    }
}
__global__ void k_hist(const void* __restrict__ ei, const float* __restrict__ ew) {
    __shared__ unsigned smn, smx;
    if (threadIdx.x == 0) { smn = 0xFFFFFFFFu; smx = 0u; }
    __syncthreads();
    unsigned mn = 0xFFFFFFFFu, mx = 0u;
    for (int e = blockIdx.x * blockDim.x + threadIdx.x; e < EE; e += gridDim.x * blockDim.x) {
        unsigned b = __float_as_uint(ew[e]);
        mn = min(mn, b); mx = max(mx, b);
        atomicAdd(&g_bcnt[load_idx(ei, (size_t)EE + e)], 1);
    }
    #pragma unroll
    for (int o = 16; o; o >>= 1) {
        mn = min(mn, __shfl_xor_sync(0xFFFFFFFFu, mn, o));
        mx = max(mx, __shfl_xor_sync(0xFFFFFFFFu, mx, o));
    }
    if ((threadIdx.x & 31) == 0) { atomicMin(&smn, mn); atomicMax(&smx, mx); }
    __syncthreads();
    if (threadIdx.x == 0) { atomicMin(&g_mm[0], smn); atomicMax(&g_mm[1], smx); }
}
__global__ void k_scan1() {
    __shared__ int s[1024];
    int i = blockIdx.x * 1024 + threadIdx.x;
    int v = (i < NN) ? g_bcnt[i] : 0;
    s[threadIdx.x] = v;
    __syncthreads();
    for (int o = 1; o < 1024; o <<= 1) {
        int t = (threadIdx.x >= o) ? s[threadIdx.x - o] : 0;
        __syncthreads();
        s[threadIdx.x] += t;
        __syncthreads();
    }
    if (i < NN) g_boff[i] = s[threadIdx.x] - v;
    if (threadIdx.x == 1023) g_part[blockIdx.x] = s[1023];
}
__global__ void k_scan2() {
    __shared__ int s[64];
    int v = (threadIdx.x < NB1) ? g_part[threadIdx.x] : 0;
    s[threadIdx.x] = v;
    __syncthreads();
    for (int o = 1; o < 64; o <<= 1) {
        int t = (threadIdx.x >= o) ? s[threadIdx.x - o] : 0;
        __syncthreads();
        s[threadIdx.x] += t;
        __syncthreads();
    }
    if (threadIdx.x < NB1) g_part[threadIdx.x] = s[threadIdx.x] - v;
}
__global__ void k_scan3() {
    int i = blockIdx.x * blockDim.x + threadIdx.x;
    for (int j = i; j < NN; j += gridDim.x * blockDim.x)
        g_boff[j] += g_part[j >> 10];
    if (i == 0) g_boff[NN] = EE;
}
__global__ void k_reorder(const void* __restrict__ ei, const float* __restrict__ ew,
                          const void* __restrict__ et) {
    float mn = __uint_as_float(g_mm[0]);
    float mx = __uint_as_float(g_mm[1]);
    float sc = 1.0f / (mx - mn + 1e-8f);
    for (int e = blockIdx.x * blockDim.x + threadIdx.x; e < EE; e += gridDim.x * blockDim.x) {
        int src = load_idx(ei, e);
        int dst = load_idx(ei, (size_t)EE + e);
        int r   = load_idx(et, e);
        int cnt = g_boff[dst + 1] - g_boff[dst];
        int pos = g_boff[dst] + atomicAdd(&g_bcur[dst], 1);
        float coef = (ew[e] - mn) * sc / (float)max(cnt, 1);
        g_emeta[pos] = make_int2(src * NS + r, __float_as_int(coef));
    }
}

// ---------------------------------------------------------------------------
// A-resident slot-loop GEMM (mma.sync split-bf16, cp.async double-buffered B).
// For y in [0, NS): C[n, y*cstride + zoff + c] = sum_k A[n,k] * B_y[k, zoff+c]
// A (both planes) loaded once per CTA; B double-buffered across slots.
// 3-term: a1*b1 + a2*b1 + a1*b2.
// ---------------------------------------------------------------------------
#define PKA 136   // A smem row halves: 272B stride
#define PNB 72    // B smem row halves: 144B stride
#define SM_APL (128 * PKA * 2)          // 34816 per plane
#define SM_BPL (128 * PNB * 2)          // 18432 per plane
#define SM_BBUF (2 * SM_BPL)            // 36864 per slot buffer (hi+lo)
#define SMEM_GEMM (2 * SM_APL + 2 * SM_BBUF)  // 143360

__global__ void __launch_bounds__(256, 1)
tc_gemm(const __nv_bfloat16* __restrict__ Ah, const __nv_bfloat16* __restrict__ Al,
        const __nv_bfloat16* __restrict__ Bh0, const __nv_bfloat16* __restrict__ Bl0,
        long strideB, int ldb, int cstride,
        float* __restrict__ C, int ldc) {
    extern __shared__ char smem[];
    int tid = threadIdx.x, wid = tid >> 5, lane = tid & 31;
    int row0 = blockIdx.x * 128;
    int zoff = blockIdx.y * 64;

    uint32_t uAh = smem_u32(smem);
    uint32_t uAl = uAh + SM_APL;
    uint32_t uB  = uAh + 2 * SM_APL;   // two buffers of SM_BBUF

    // ---- A: 128 rows x 256B per plane ----
    #pragma unroll
    for (int i = 0; i < 8; i++) {
        int c = tid + i * 256;
        int row = c >> 4, col = c & 15;
        int gr = row0 + row;
        uint32_t ok = (gr < NN) ? 16u : 0u;
        int grc = gr < NN ? gr : NN - 1;
        cp16(uAh + row * 272 + col * 16,
             (const char*)(Ah + (size_t)grc * FF) + col * 16, ok);
        cp16(uAl + row * 272 + col * 16,
             (const char*)(Al + (size_t)grc * FF) + col * 16, ok);
    }
    // ---- B slot 0 into buf 0 ----
    {
        const __nv_bfloat16* bh = Bh0 + zoff;
        const __nv_bfloat16* bl = Bl0 + zoff;
        #pragma unroll
        for (int i = 0; i < 4; i++) {
            int c = tid + i * 256;
            int row = c >> 3, col = c & 7;
            cp16(uB + row * 144 + col * 16,
                 (const char*)(bh + (size_t)row * ldb) + col * 16, 16u);
            cp16(uB + SM_BPL + row * 144 + col * 16,
                 (const char*)(bl + (size_t)row * ldb) + col * 16, 16u);
        }
    }
    asm volatile("cp.async.commit_group;" ::: "memory");

    int r = lane & 7, j = lane >> 3;
    int amrow = wid * 16 + r + 8 * (j & 1);
    int bncol0 = 8 * (j >> 1);
    int orow = row0 + wid * 16 + lane / 4;
    int oc0 = 2 * (lane & 3);

    for (int y = 0; y < NS; y++) {
        uint32_t ubuf = uB + (y & 1) * SM_BBUF;
        if (y + 1 < NS) {
            uint32_t unext = uB + ((y + 1) & 1) * SM_BBUF;
            const __nv_bfloat16* bh = Bh0 + (size_t)(y + 1) * strideB + zoff;
            const __nv_bfloat16* bl = Bl0 + (size_t)(y + 1) * strideB + zoff;
            #pragma unroll
            for (int i = 0; i < 4; i++) {
                int c = tid + i * 256;
                int row = c >> 3, col = c & 7;
                cp16(unext + row * 144 + col * 16,
                     (const char*)(bh + (size_t)row * ldb) + col * 16, 16u);
                cp16(unext + SM_BPL + row * 144 + col * 16,
                     (const char*)(bl + (size_t)row * ldb) + col * 16, 16u);
            }
            asm volatile("cp.async.commit_group;" ::: "memory");
            asm volatile("cp.async.wait_group 1;" ::: "memory");
        } else {
            asm volatile("cp.async.wait_group 0;" ::: "memory");
        }
        __syncthreads();

        float acc[8][4];
        #pragma unroll
        for (int i = 0; i < 8; i++)
            #pragma unroll
            for (int q = 0; q < 4; q++) acc[i][q] = 0.f;

        uint32_t ubh = ubuf, ubl = ubuf + SM_BPL;
        #pragma unroll
        for (int ks = 0; ks < 8; ks++) {
            int k0 = ks * 16;
            uint32_t ah[4], al[4];
            int akcol = k0 + 8 * (j >> 1);
            ldsm_x4(ah[0], ah[1], ah[2], ah[3], uAh + (amrow * PKA + akcol) * 2);
            ldsm_x4(al[0], al[1], al[2], al[3], uAl + (amrow * PKA + akcol) * 2);
            int bkrow = k0 + r + 8 * (j & 1);
            #pragma unroll
            for (int p = 0; p < 4; p++) {
                uint32_t bh0r, bh1r, bh2r, bh3r, bl0r, bl1r, bl2r, bl3r;
                ldsm_x4t(bh0r, bh1r, bh2r, bh3r, ubh + (bkrow * PNB + p * 16 + bncol0) * 2);
                ldsm_x4t(bl0r, bl1r, bl2r, bl3r, ubl + (bkrow * PNB + p * 16 + bncol0) * 2);
                mma_bf16(acc[2 * p + 0], ah, bh0r, bh1r);
                mma_bf16(acc[2 * p + 0], al, bh0r, bh1r);
                mma_bf16(acc[2 * p + 0], ah, bl0r, bl1r);
                mma_bf16(acc[2 * p + 1], ah, bh2r, bh3r);
                mma_bf16(acc[2 * p + 1], al, bh2r, bh3r);
                mma_bf16(acc[2 * p + 1], ah, bl2r, bl3r);
            }
        }

        // epilogue for slot y
        float* Cw = C + y * cstride + zoff;
        #pragma unroll
        for (int nt = 0; nt < 8; nt++) {
            int col = nt * 8 + oc0;
            if (orow < NN)
                *(float2*)&Cw[(size_t)orow * ldc + col] =
                    make_float2(acc[nt][0], acc[nt][1]);
            if (orow + 8 < NN)
                *(float2*)&Cw[(size_t)(orow + 8) * ldc + col] =
                    make_float2(acc[nt][2], acc[nt][3]);
        }
        __syncthreads();   // buf reuse barrier
    }
}

// ---------------------------------------------------------------------------
// Layer-1 aggregate: h = relu(Y1[root] + bias + msgs) -> bf16 planes (fused).
// ---------------------------------------------------------------------------
__global__ void k_agg1(const float* __restrict__ Y, const float* __restrict__ bias,
                       __nv_bfloat16* __restrict__ hh, __nv_bfloat16* __restrict__ hl) {
    int w = (blockIdx.x * blockDim.x + threadIdx.x) >> 5;
    int lane = threadIdx.x & 31;
    if (w >= NN) return;
    int s0 = g_boff[w], s1 = g_boff[w + 1];

    float4 rv = *(const float4*)(Y + ((size_t)w * NS + 8) * HH + lane * 4);
    float4 bv = *(const float4*)(bias + lane * 4);
    float a0 = rv.x + bv.x, a1 = rv.y + bv.y, a2 = rv.z + bv.z, a3 = rv.w + bv.w;

    for (int base = s0; base < s1; base += 32) {
        int idx = base + lane;
        int2 m = (idx < s1) ? g_emeta[idx] : make_int2(0, 0);
        int cnt = min(32, s1 - base);
        for (int jj = 0; jj < cnt; jj++) {
            int sr   = __shfl_sync(0xFFFFFFFFu, m.x, jj);
            float cf = __int_as_float(__shfl_sync(0xFFFFFFFFu, m.y, jj));
            float4 yv = *(const float4*)(Y + (size_t)sr * HH + lane * 4);
            a0 += cf * yv.x; a1 += cf * yv.y; a2 += cf * yv.z; a3 += cf * yv.w;
        }
    }
    float vs[4] = {fmaxf(a0, 0.f), fmaxf(a1, 0.f), fmaxf(a2, 0.f), fmaxf(a3, 0.f)};
    split4_store(vs, hh + (size_t)w * FF, hl + (size_t)w * FF, lane);
}

// ---------------------------------------------------------------------------
// Layer-2 aggregate: out = Y2[root] + bias + msgs (fp32).
// ---------------------------------------------------------------------------
__global__ void k_agg2(const float* __restrict__ Y, const float* __restrict__ bias,
                       float* __restrict__ out) {
    int w = (blockIdx.x * blockDim.x + threadIdx.x) >> 5;
    int lane = threadIdx.x & 31;
    if (w >= NN) return;
    int s0 = g_boff[w], s1 = g_boff[w + 1];

    float2 rv = *(const float2*)(Y + ((size_t)w * NS + 8) * OO + lane * 2);
    float a0 = rv.x + bias[lane * 2], a1 = rv.y + bias[lane * 2 + 1];

    for (int base = s0; base < s1; base += 32) {
        int idx = base + lane;
        int2 m = (idx < s1) ? g_emeta[idx] : make_int2(0, 0);
        int cnt = min(32, s1 - base);
        for (int jj = 0; jj < cnt; jj++) {
            int sr   = __shfl_sync(0xFFFFFFFFu, m.x, jj);
            float cf = __int_as_float(__shfl_sync(0xFFFFFFFFu, m.y, jj));
            float2 yv = *(const float2*)(Y + (size_t)sr * OO + lane * 2);
            a0 += cf * yv.x; a1 += cf * yv.y;
        }
    }
    *(float2*)&out[(size_t)w * OO + lane * 2] = make_float2(a0, a1);
}

// ---------------------------------------------------------------------------
// Launch
// ---------------------------------------------------------------------------
extern "C" void kernel_launch(void* const* d_in, const int* in_sizes, int n_in,
                              void* d_out, int out_size) {
    const float* x     = (const float*)d_in[0];
    const void*  ei    = d_in[1];
    const float* ew    = (const float*)d_in[2];
    const void*  et    = d_in[3];
    const float* W1    = (const float*)d_in[4];
    const float* root1 = (const float*)d_in[5];
    const float* bias1 = (const float*)d_in[6];
    const float* W2    = (const float*)d_in[7];
    const float* root2 = (const float*)d_in[8];
    const float* bias2 = (const float*)d_in[9];
    float* out = (float*)d_out;

    void *pY, *pAh, *pAl, *pWh, *pWl;
    cudaGetSymbolAddress(&pY, g_Y);
    cudaGetSymbolAddress(&pAh, g_Ah);
    cudaGetSymbolAddress(&pAl, g_Al);
    cudaGetSymbolAddress(&pWh, g_Wh);
    cudaGetSymbolAddress(&pWl, g_Wl);
    const float* Yp = (const float*)pY;
    float*       Ym = (float*)pY;
    __nv_bfloat16* Ah = (__nv_bfloat16*)pAh;
    __nv_bfloat16* Al = (__nv_bfloat16*)pAl;
    __nv_bfloat16* Wh = (__nv_bfloat16*)pWh;
    __nv_bfloat16* Wl = (__nv_bfloat16*)pWl;

    const int GB = (NN + 127) / 128;   // 391 row tiles
    const int GA = (NN * 32 + 255) / 256;
    cudaFuncSetAttribute(tc_gemm, cudaFuncAttributeMaxDynamicSharedMemorySize, SMEM_GEMM);

    k_zerodet<<<256, 256>>>(ei);                                     // 1
    k_split<<<(NN * FF / 4 + 255) / 256, 256>>>(x, Ah, Al, NN * FF / 4);          // 2
    k_splitW<<<((RR * FF * HH + FF * HH) / 4 + 255) / 256, 256>>>(   // 3
        W1, RR * FF * HH / 4, root1, FF * HH / 4, Wh, Wl);
    // Y1 (slots 0..8): grid (391, 2) z-halves, CTA loops over 9 slots
    tc_gemm<<<dim3(GB, 2), 256, SMEM_GEMM>>>(                        // 4 (profiled)
        Ah, Al, Wh, Wl, (long)FF * HH, HH, HH, Ym, NS * HH);

    k_hist<<<1024, 256>>>(ei, ew);                                   // 5
    k_scan1<<<NB1, 1024>>>();                                        // 6
    k_scan2<<<1, 64>>>();                                            // 7
    k_scan3<<<256, 256>>>();                                         // 8
    k_reorder<<<1024, 256>>>(ei, ew, et);                            // 9

    // h = relu(root + bias1 + agg) -> bf16 planes
    k_agg1<<<GA, 256>>>(Yp, bias1, Ah, Al);                          // 10

    k_splitW<<<((RR * HH * OO + HH * OO) / 4 + 255) / 256, 256>>>(   // 11
        W2, RR * HH * OO / 4, root2, HH * OO / 4, Wh, Wl);
    // Y2 (slots 0..8): grid (391, 1), 64-wide slots
    tc_gemm<<<dim3(GB, 1), 256, SMEM_GEMM>>>(                        // 12
        Ah, Al, Wh, Wl, (long)HH * OO, OO, OO, Ym, NS * OO);

    // out = root + bias2 + agg
    k_agg2<<<GA, 256>>>(Yp, bias2, out);                             // 13
}

// round 13
// speedup vs baseline: 1.1446x; 1.1446x over previous
#include <cuda_runtime.h>
#include <cuda_fp16.h>
#include <stdint.h>

// Problem constants
#define NN 50000
#define EE 600000
#define FF 128
#define HH 128
#define OO 64
#define RR 8
#define NS 9                       // 8 relations + root slot
#define NB1 ((NN + 1023) / 1024)   // 49 scan blocks

// ---------------------------------------------------------------------------
// Device scratch
// ---------------------------------------------------------------------------
__device__ float   g_Y[(size_t)NN * NS * HH];  // 230.4 MB projection buf
__device__ __half  g_Ah[(size_t)NN * FF];      // A hi plane (fp16)
__device__ __half  g_Al[(size_t)NN * FF];      // A lo plane (fp16 residual)
__device__ __half  g_Wh[NS * FF * HH];         // W hi (slots 0..8)
__device__ int     g_bcnt[NN];
__device__ int     g_bcur[NN];
__device__ int     g_boff[NN + 1];
__device__ int     g_part[64];
__device__ int2    g_emeta[EE];                // sorted: {src*9+r, coef}
__device__ unsigned g_mm[2];
__device__ int     g_is64;

// ---------------------------------------------------------------------------
// Helpers
// ---------------------------------------------------------------------------
__device__ __forceinline__ int load_idx(const void* p, size_t i) {
    return g_is64 ? (int)((const long long*)p)[i] : ((const int*)p)[i];
}
__device__ __forceinline__ uint32_t smem_u32(const void* p) {
    uint32_t a;
    asm("{ .reg .u64 t; cvta.to.shared.u64 t, %1; cvt.u32.u64 %0, t; }"
        : "=r"(a) : "l"(p));
    return a;
}
__device__ __forceinline__ void cp16(uint32_t d, const void* s, uint32_t nbytes) {
    asm volatile("cp.async.cg.shared.global [%0], [%1], 16, %2;"
                 :: "r"(d), "l"(s), "r"(nbytes) : "memory");
}
__device__ __forceinline__ void ldsm_x4(uint32_t& r0, uint32_t& r1,
                                        uint32_t& r2, uint32_t& r3, uint32_t a) {
    asm volatile("ldmatrix.sync.aligned.m8n8.x4.shared.b16 {%0,%1,%2,%3}, [%4];"
                 : "=r"(r0), "=r"(r1), "=r"(r2), "=r"(r3) : "r"(a));
}
__device__ __forceinline__ void ldsm_x4t(uint32_t& r0, uint32_t& r1,
                                         uint32_t& r2, uint32_t& r3, uint32_t a) {
    asm volatile("ldmatrix.sync.aligned.m8n8.x4.trans.shared.b16 {%0,%1,%2,%3}, [%4];"
                 : "=r"(r0), "=r"(r1), "=r"(r2), "=r"(r3) : "r"(a));
}
__device__ __forceinline__ void mma_f16(float* c, const uint32_t* a,
                                        uint32_t b0, uint32_t b1) {
    asm volatile(
        "mma.sync.aligned.m16n8k16.row.col.f32.f16.f16.f32 "
        "{%0,%1,%2,%3}, {%4,%5,%6,%7}, {%8,%9}, {%0,%1,%2,%3};"
        : "+f"(c[0]), "+f"(c[1]), "+f"(c[2]), "+f"(c[3])
        : "r"(a[0]), "r"(a[1]), "r"(a[2]), "r"(a[3]), "r"(b0), "r"(b1));
}
__device__ __forceinline__ void split1(float v, unsigned short& h, unsigned short& l) {
    __half b1 = __float2half_rn(v);
    __half b2 = __float2half_rn(v - __half2float(b1));
    h = __half_as_ushort(b1);
    l = __half_as_ushort(b2);
}
__device__ __forceinline__ void split4_store(const float* vs,
                                             __half* hi, __half* lo, int i) {
    unsigned short h[4], l[4];
    #pragma unroll
    for (int j = 0; j < 4; j++) split1(vs[j], h[j], l[j]);
    uint2 ph, pl;
    ph.x = (uint32_t)h[0] | ((uint32_t)h[1] << 16);
    ph.y = (uint32_t)h[2] | ((uint32_t)h[3] << 16);
    pl.x = (uint32_t)l[0] | ((uint32_t)l[1] << 16);
    pl.y = (uint32_t)l[2] | ((uint32_t)l[3] << 16);
    ((uint2*)hi)[i] = ph;
    ((uint2*)lo)[i] = pl;
}

// ---------------------------------------------------------------------------
// Split fp32 -> fp16 hi/lo planes (x / h). Hi-only variant for weights.
// ---------------------------------------------------------------------------
__global__ void k_split(const float* __restrict__ src,
                        __half* __restrict__ hi, __half* __restrict__ lo, int n4) {
    int i = blockIdx.x * blockDim.x + threadIdx.x;
    if (i >= n4) return;
    float4 v = ((const float4*)src)[i];
    float vs[4] = {v.x, v.y, v.z, v.w};
    split4_store(vs, hi, lo, i);
}

// Weights: hi plane only (2-term scheme drops b-residual). Two sources.
__global__ void k_splitW(const float* __restrict__ srcA, int n4a,
                         const float* __restrict__ srcB, int n4b,
                         __half* __restrict__ hi) {
    int i = blockIdx.x * blockDim.x + threadIdx.x;
    if (i >= n4a + n4b) return;
    float4 v = (i < n4a) ? ((const float4*)srcA)[i]
                         : ((const float4*)srcB)[i - n4a];
    unsigned short h0, h1, h2, h3, dummy;
    split1(v.x, h0, dummy); split1(v.y, h1, dummy);
    split1(v.z, h2, dummy); split1(v.w, h3, dummy);
    uint2 ph;
    ph.x = (uint32_t)h0 | ((uint32_t)h1 << 16);
    ph.y = (uint32_t)h2 | ((uint32_t)h3 << 16);
    ((uint2*)hi)[i] = ph;
}

// ---------------------------------------------------------------------------
// Edge preprocessing
// ---------------------------------------------------------------------------
__global__ void k_zerodet(const void* ei) {
    int i = blockIdx.x * blockDim.x + threadIdx.x;
    for (int j = i; j < NN; j += gridDim.x * blockDim.x) { g_bcnt[j] = 0; g_bcur[j] = 0; }
    if (i == 0) {
        g_mm[0] = 0xFFFFFFFFu; g_mm[1] = 0u;
        const int* p = (const int*)ei;
        int nz = 0;
        for (int k = 1; k < 2001; k += 2) nz |= p[k];
        g_is64 = (nz == 0) ? 1 : 0;
    }
}
__global__ void k_hist(const void* __restrict__ ei, const float* __restrict__ ew) {
    __shared__ unsigned smn, smx;
    if (threadIdx.x == 0) { smn = 0xFFFFFFFFu; smx = 0u; }
    __syncthreads();
    unsigned mn = 0xFFFFFFFFu, mx = 0u;
    for (int e = blockIdx.x * blockDim.x + threadIdx.x; e < EE; e += gridDim.x * blockDim.x) {
        unsigned b = __float_as_uint(ew[e]);
        mn = min(mn, b); mx = max(mx, b);
        atomicAdd(&g_bcnt[load_idx(ei, (size_t)EE + e)], 1);
    }
    #pragma unroll
    for (int o = 16; o; o >>= 1) {
        mn = min(mn, __shfl_xor_sync(0xFFFFFFFFu, mn, o));
        mx = max(mx, __shfl_xor_sync(0xFFFFFFFFu, mx, o));
    }
    if ((threadIdx.x & 31) == 0) { atomicMin(&smn, mn); atomicMax(&smx, mx); }
    __syncthreads();
    if (threadIdx.x == 0) { atomicMin(&g_mm[0], smn); atomicMax(&g_mm[1], smx); }
}
__global__ void k_scan1() {
    __shared__ int s[1024];
    int i = blockIdx.x * 1024 + threadIdx.x;
    int v = (i < NN) ? g_bcnt[i] : 0;
    s[threadIdx.x] = v;
    __syncthreads();
    for (int o = 1; o < 1024; o <<= 1) {
        int t = (threadIdx.x >= o) ? s[threadIdx.x - o] : 0;
        __syncthreads();
        s[threadIdx.x] += t;
        __syncthreads();
    }
    if (i < NN) g_boff[i] = s[threadIdx.x] - v;
    if (threadIdx.x == 1023) g_part[blockIdx.x] = s[1023];
}
__global__ void k_scan2() {
    __shared__ int s[64];
    int v = (threadIdx.x < NB1) ? g_part[threadIdx.x] : 0;
    s[threadIdx.x] = v;
    __syncthreads();
    for (int o = 1; o < 64; o <<= 1) {
        int t = (threadIdx.x >= o) ? s[threadIdx.x - o] : 0;
        __syncthreads();
        s[threadIdx.x] += t;
        __syncthreads();
    }
    if (threadIdx.x < NB1) g_part[threadIdx.x] = s[threadIdx.x] - v;
}
__global__ void k_scan3() {
    int i = blockIdx.x * blockDim.x + threadIdx.x;
    for (int j = i; j < NN; j += gridDim.x * blockDim.x)
        g_boff[j] += g_part[j >> 10];
    if (i == 0) g_boff[NN] = EE;
}
__global__ void k_reorder(const void* __restrict__ ei, const float* __restrict__ ew,
                          const void* __restrict__ et) {
    float mn = __uint_as_float(g_mm[0]);
    float mx = __uint_as_float(g_mm[1]);
    float sc = 1.0f / (mx - mn + 1e-8f);
    for (int e = blockIdx.x * blockDim.x + threadIdx.x; e < EE; e += gridDim.x * blockDim.x) {
        int src = load_idx(ei, e);
        int dst = load_idx(ei, (size_t)EE + e);
        int r   = load_idx(et, e);
        int cnt = g_boff[dst + 1] - g_boff[dst];
        int pos = g_boff[dst] + atomicAdd(&g_bcur[dst], 1);
        float coef = (ew[e] - mn) * sc / (float)max(cnt, 1);
        g_emeta[pos] = make_int2(src * NS + r, __float_as_int(coef));
    }
}

// ---------------------------------------------------------------------------
// mma.sync fp16 2-term GEMM with async loads (R11 structure).
// C[n, y*cstride + z*64 + c] = sum_k A[n,k] * B_y[k, z*64+c]
// A = a1 + a2 (fp16 hi/lo planes); B = b1 only. acc = a1*b1 + a2*b1.
// Full tiles loaded once via cp.async, one sync, 8 uninterrupted k16 steps.
// ---------------------------------------------------------------------------
#define PKA 136   // A smem row halves: 272B stride
#define PNB 72    // B smem row halves: 144B stride
#define SM_APL (128 * PKA * 2)          // 34816 per plane
#define SM_BPL (128 * PNB * 2)          // 18432
#define SMEM_GEMM (2 * SM_APL + SM_BPL) // 88064 -> 2 CTAs/SM

__global__ void __launch_bounds__(256, 2)
tc_gemm(const __half* __restrict__ Ah, const __half* __restrict__ Al,
        const __half* __restrict__ Bh0,
        long strideB, int ldb, int cstride,
        float* __restrict__ C, int ldc) {
    extern __shared__ char smem[];
    int tid = threadIdx.x, wid = tid >> 5, lane = tid & 31;
    int row0 = blockIdx.x * 128;
    const __half* Bh = Bh0 + (size_t)blockIdx.y * strideB + blockIdx.z * 64;
    float* Cw = C + blockIdx.y * cstride + blockIdx.z * 64;

    uint32_t uAh = smem_u32(smem);
    uint32_t uAl = uAh + SM_APL;
    uint32_t uBh = uAh + 2 * SM_APL;

    // ---- A: 128 rows x 256B per plane ----
    #pragma unroll
    for (int i = 0; i < 8; i++) {
        int c = tid + i * 256;
        int row = c >> 4, col = c & 15;
        int gr = row0 + row;
        uint32_t ok = (gr < NN) ? 16u : 0u;
        int grc = gr < NN ? gr : NN - 1;
        cp16(uAh + row * 272 + col * 16,
             (const char*)(Ah + (size_t)grc * FF) + col * 16, ok);
        cp16(uAl + row * 272 + col * 16,
             (const char*)(Al + (size_t)grc * FF) + col * 16, ok);
    }
    // ---- B: 128 k-rows x 128B, hi plane only ----
    #pragma unroll
    for (int i = 0; i < 4; i++) {
        int c = tid + i * 256;
        int row = c >> 3, col = c & 7;
        cp16(uBh + row * 144 + col * 16,
             (const char*)(Bh + (size_t)row * ldb) + col * 16, 16u);
    }
    asm volatile("cp.async.commit_group;" ::: "memory");
    asm volatile("cp.async.wait_group 0;" ::: "memory");
    __syncthreads();

    float acc[8][4];
    #pragma unroll
    for (int i = 0; i < 8; i++)
        #pragma unroll
        for (int q = 0; q < 4; q++) acc[i][q] = 0.f;

    int r = lane & 7, j = lane >> 3;
    int amrow = wid * 16 + r + 8 * (j & 1);
    int bncol0 = 8 * (j >> 1);

    #pragma unroll
    for (int ks = 0; ks < 8; ks++) {
        int k0 = ks * 16;
        uint32_t ah[4], al[4];
        int akcol = k0 + 8 * (j >> 1);
        ldsm_x4(ah[0], ah[1], ah[2], ah[3], uAh + (amrow * PKA + akcol) * 2);
        ldsm_x4(al[0], al[1], al[2], al[3], uAl + (amrow * PKA + akcol) * 2);
        int bkrow = k0 + r + 8 * (j & 1);
        #pragma unroll
        for (int p = 0; p < 4; p++) {
            uint32_t b0, b1, b2, b3;
            ldsm_x4t(b0, b1, b2, b3, uBh + (bkrow * PNB + p * 16 + bncol0) * 2);
            mma_f16(acc[2 * p + 0], ah, b0, b1);   // a1*b1
            mma_f16(acc[2 * p + 0], al, b0, b1);   // a2*b1
            mma_f16(acc[2 * p + 1], ah, b2, b3);
            mma_f16(acc[2 * p + 1], al, b2, b3);
        }
    }

    // ---- epilogue ----
    int orow = row0 + wid * 16 + lane / 4;
    int oc0 = 2 * (lane & 3);
    #pragma unroll
    for (int nt = 0; nt < 8; nt++) {
        int col = nt * 8 + oc0;
        if (orow < NN)
            *(float2*)&Cw[(size_t)orow * ldc + col] =
                make_float2(acc[nt][0], acc[nt][1]);
        if (orow + 8 < NN)
            *(float2*)&Cw[(size_t)(orow + 8) * ldc + col] =
                make_float2(acc[nt][2], acc[nt][3]);
    }
}

// ---------------------------------------------------------------------------
// Layer-1 aggregate: h = relu(Y1[root] + bias + msgs) -> fp16 planes (fused).
// ---------------------------------------------------------------------------
__global__ void k_agg1(const float* __restrict__ Y, const float* __restrict__ bias,
                       __half* __restrict__ hh, __half* __restrict__ hl) {
    int w = (blockIdx.x * blockDim.x + threadIdx.x) >> 5;
    int lane = threadIdx.x & 31;
    if (w >= NN) return;
    int s0 = g_boff[w], s1 = g_boff[w + 1];

    float4 rv = *(const float4*)(Y + ((size_t)w * NS + 8) * HH + lane * 4);
    float4 bv = *(const float4*)(bias + lane * 4);
    float a0 = rv.x + bv.x, a1 = rv.y + bv.y, a2 = rv.z + bv.z, a3 = rv.w + bv.w;

    for (int base = s0; base < s1; base += 32) {
        int idx = base + lane;
        int2 m = (idx < s1) ? g_emeta[idx] : make_int2(0, 0);
        int cnt = min(32, s1 - base);
        for (int jj = 0; jj < cnt; jj++) {
            int sr   = __shfl_sync(0xFFFFFFFFu, m.x, jj);
            float cf = __int_as_float(__shfl_sync(0xFFFFFFFFu, m.y, jj));
            float4 yv = *(const float4*)(Y + (size_t)sr * HH + lane * 4);
            a0 += cf * yv.x; a1 += cf * yv.y; a2 += cf * yv.z; a3 += cf * yv.w;
        }
    }
    float vs[4] = {fmaxf(a0, 0.f), fmaxf(a1, 0.f), fmaxf(a2, 0.f), fmaxf(a3, 0.f)};
    split4_store(vs, hh + (size_t)w * FF, hl + (size_t)w * FF, lane);
}

// ---------------------------------------------------------------------------
// Layer-2 aggregate: out = Y2[root] + bias + msgs (fp32).
// ---------------------------------------------------------------------------
__global__ void k_agg2(const float* __restrict__ Y, const float* __restrict__ bias,
                       float* __restrict__ out) {
    int w = (blockIdx.x * blockDim.x + threadIdx.x) >> 5;
    int lane = threadIdx.x & 31;
    if (w >= NN) return;
    int s0 = g_boff[w], s1 = g_boff[w + 1];

    float2 rv = *(const float2*)(Y + ((size_t)w * NS + 8) * OO + lane * 2);
    float a0 = rv.x + bias[lane * 2], a1 = rv.y + bias[lane * 2 + 1];

    for (int base = s0; base < s1; base += 32) {
        int idx = base + lane;
        int2 m = (idx < s1) ? g_emeta[idx] : make_int2(0, 0);
        int cnt = min(32, s1 - base);
        for (int jj = 0; jj < cnt; jj++) {
            int sr   = __shfl_sync(0xFFFFFFFFu, m.x, jj);
            float cf = __int_as_float(__shfl_sync(0xFFFFFFFFu, m.y, jj));
            float2 yv = *(const float2*)(Y + (size_t)sr * OO + lane * 2);
            a0 += cf * yv.x; a1 += cf * yv.y;
        }
    }
    *(float2*)&out[(size_t)w * OO + lane * 2] = make_float2(a0, a1);
}

// ---------------------------------------------------------------------------
// Launch
// ---------------------------------------------------------------------------
extern "C" void kernel_launch(void* const* d_in, const int* in_sizes, int n_in,
                              void* d_out, int out_size) {
    const float* x     = (const float*)d_in[0];
    const void*  ei    = d_in[1];
    const float* ew    = (const float*)d_in[2];
    const void*  et    = d_in[3];
    const float* W1    = (const float*)d_in[4];
    const float* root1 = (const float*)d_in[5];
    const float* bias1 = (const float*)d_in[6];
    const float* W2    = (const float*)d_in[7];
    const float* root2 = (const float*)d_in[8];
    const float* bias2 = (const float*)d_in[9];
    float* out = (float*)d_out;

    void *pY, *pAh, *pAl, *pWh;
    cudaGetSymbolAddress(&pY, g_Y);
    cudaGetSymbolAddress(&pAh, g_Ah);
    cudaGetSymbolAddress(&pAl, g_Al);
    cudaGetSymbolAddress(&pWh, g_Wh);
    const float* Yp = (const float*)pY;
    float*       Ym = (float*)pY;
    __half* Ah = (__half*)pAh;
    __half* Al = (__half*)pAl;
    __half* Wh = (__half*)pWh;

    const int GB = (NN + 127) / 128;   // 391 row tiles
    const int GA = (NN * 32 + 255) / 256;
    cudaFuncSetAttribute(tc_gemm, cudaFuncAttributeMaxDynamicSharedMemorySize, SMEM_GEMM);

    k_zerodet<<<256, 256>>>(ei);                                     // 1
    k_split<<<(NN * FF / 4 + 255) / 256, 256>>>(x, Ah, Al, NN * FF / 4);          // 2
    k_splitW<<<((RR * FF * HH + FF * HH) / 4 + 255) / 256, 256>>>(   // 3
        W1, RR * FF * HH / 4, root1, FF * HH / 4, Wh);
    // Y1 (slots 0..8): grid (391, 9, 2)
    tc_gemm<<<dim3(GB, NS, 2), 256, SMEM_GEMM>>>(                    // 4 (profiled)
        Ah, Al, Wh, (long)FF * HH, HH, HH, Ym, NS * HH);

    k_hist<<<1024, 256>>>(ei, ew);                                   // 5
    k_scan1<<<NB1, 1024>>>();                                        // 6
    k_scan2<<<1, 64>>>();                                            // 7
    k_scan3<<<256, 256>>>();                                         // 8
    k_reorder<<<1024, 256>>>(ei, ew, et);                            // 9

    // h = relu(root + bias1 + agg) -> fp16 planes
    k_agg1<<<GA, 256>>>(Yp, bias1, Ah, Al);                          // 10

    k_splitW<<<((RR * HH * OO + HH * OO) / 4 + 255) / 256, 256>>>(   // 11
        W2, RR * HH * OO / 4, root2, HH * OO / 4, Wh);
    // Y2 (slots 0..8): grid (391, 9, 1)
    tc_gemm<<<dim3(GB, NS, 1), 256, SMEM_GEMM>>>(                    // 12
        Ah, Al, Wh, (long)HH * OO, OO, OO, Ym, NS * OO);

    // out = root + bias2 + agg
    k_agg2<<<GA, 256>>>(Yp, bias2, out);                             // 13
}

// round 14
// speedup vs baseline: 1.1659x; 1.0187x over previous
#include <cuda_runtime.h>
#include <cuda_fp16.h>
#include <stdint.h>

// Problem constants
#define NN 50000
#define EE 600000
#define FF 128
#define HH 128
#define OO 64
#define RR 8
#define NS 9                       // 8 relations + root slot
#define NB1 ((NN + 1023) / 1024)   // 49 scan blocks

// ---------------------------------------------------------------------------
// Device scratch
// ---------------------------------------------------------------------------
__device__ float   g_Y[(size_t)NN * NS * HH];  // 230.4 MB projection buf
__device__ __half  g_Ah[(size_t)NN * FF];      // A hi plane (fp16)
__device__ __half  g_Al[(size_t)NN * FF];      // A lo plane (fp16 residual)
__device__ __half  g_Wh[NS * FF * HH];         // W hi (slots 0..8)
__device__ int     g_bcnt[NN];
__device__ int     g_bcur[NN];
__device__ int     g_boff[NN + 1];
__device__ int     g_part[64];
__device__ int2    g_emeta[EE];                // sorted: {src*9+r, coef}
__device__ unsigned g_mm[2];
__device__ int     g_is64;

// ---------------------------------------------------------------------------
// Helpers
// ---------------------------------------------------------------------------
__device__ __forceinline__ int load_idx(const void* p, size_t i) {
    return g_is64 ? (int)((const long long*)p)[i] : ((const int*)p)[i];
}
__device__ __forceinline__ uint32_t smem_u32(const void* p) {
    uint32_t a;
    asm("{ .reg .u64 t; cvta.to.shared.u64 t, %1; cvt.u32.u64 %0, t; }"
        : "=r"(a) : "l"(p));
    return a;
}
__device__ __forceinline__ void cp16(uint32_t d, const void* s, uint32_t nbytes) {
    asm volatile("cp.async.cg.shared.global [%0], [%1], 16, %2;"
                 :: "r"(d), "l"(s), "r"(nbytes) : "memory");
}
__device__ __forceinline__ void ldsm_x4(uint32_t& r0, uint32_t& r1,
                                        uint32_t& r2, uint32_t& r3, uint32_t a) {
    asm volatile("ldmatrix.sync.aligned.m8n8.x4.shared.b16 {%0,%1,%2,%3}, [%4];"
                 : "=r"(r0), "=r"(r1), "=r"(r2), "=r"(r3) : "r"(a));
}
__device__ __forceinline__ void ldsm_x4t(uint32_t& r0, uint32_t& r1,
                                         uint32_t& r2, uint32_t& r3, uint32_t a) {
    asm volatile("ldmatrix.sync.aligned.m8n8.x4.trans.shared.b16 {%0,%1,%2,%3}, [%4];"
                 : "=r"(r0), "=r"(r1), "=r"(r2), "=r"(r3) : "r"(a));
}
__device__ __forceinline__ void mma_f16(float* c, const uint32_t* a,
                                        uint32_t b0, uint32_t b1) {
    asm volatile(
        "mma.sync.aligned.m16n8k16.row.col.f32.f16.f16.f32 "
        "{%0,%1,%2,%3}, {%4,%5,%6,%7}, {%8,%9}, {%0,%1,%2,%3};"
        : "+f"(c[0]), "+f"(c[1]), "+f"(c[2]), "+f"(c[3])
        : "r"(a[0]), "r"(a[1]), "r"(a[2]), "r"(a[3]), "r"(b0), "r"(b1));
}
__device__ __forceinline__ void split1(float v, unsigned short& h, unsigned short& l) {
    __half b1 = __float2half_rn(v);
    __half b2 = __float2half_rn(v - __half2float(b1));
    h = __half_as_ushort(b1);
    l = __half_as_ushort(b2);
}
__device__ __forceinline__ void split4_store(const float* vs,
                                             __half* hi, __half* lo, int i) {
    unsigned short h[4], l[4];
    #pragma unroll
    for (int j = 0; j < 4; j++) split1(vs[j], h[j], l[j]);
    uint2 ph, pl;
    ph.x = (uint32_t)h[0] | ((uint32_t)h[1] << 16);
    ph.y = (uint32_t)h[2] | ((uint32_t)h[3] << 16);
    pl.x = (uint32_t)l[0] | ((uint32_t)l[1] << 16);
    pl.y = (uint32_t)l[2] | ((uint32_t)l[3] << 16);
    ((uint2*)hi)[i] = ph;
    ((uint2*)lo)[i] = pl;
}

// ---------------------------------------------------------------------------
// Split fp32 -> fp16 hi/lo planes (x / h). Hi-only variant for weights.
// ---------------------------------------------------------------------------
__global__ void k_split(const float* __restrict__ src,
                        __half* __restrict__ hi, __half* __restrict__ lo, int n4) {
    int i = blockIdx.x * blockDim.x + threadIdx.x;
    if (i >= n4) return;
    float4 v = ((const float4*)src)[i];
    float vs[4] = {v.x, v.y, v.z, v.w};
    split4_store(vs, hi, lo, i);
}

__global__ void k_splitW(const float* __restrict__ srcA, int n4a,
                         const float* __restrict__ srcB, int n4b,
                         __half* __restrict__ hi) {
    int i = blockIdx.x * blockDim.x + threadIdx.x;
    if (i >= n4a + n4b) return;
    float4 v = (i < n4a) ? ((const float4*)srcA)[i]
                         : ((const float4*)srcB)[i - n4a];
    unsigned short h0, h1, h2, h3, dummy;
    split1(v.x, h0, dummy); split1(v.y, h1, dummy);
    split1(v.z, h2, dummy); split1(v.w, h3, dummy);
    uint2 ph;
    ph.x = (uint32_t)h0 | ((uint32_t)h1 << 16);
    ph.y = (uint32_t)h2 | ((uint32_t)h3 << 16);
    ((uint2*)hi)[i] = ph;
}

// ---------------------------------------------------------------------------
// Edge preprocessing
// ---------------------------------------------------------------------------
__global__ void k_zerodet(const void* ei) {
    int i = blockIdx.x * blockDim.x + threadIdx.x;
    for (int j = i; j < NN; j += gridDim.x * blockDim.x) { g_bcnt[j] = 0; g_bcur[j] = 0; }
    if (i == 0) {
        g_mm[0] = 0xFFFFFFFFu; g_mm[1] = 0u;
        const int* p = (const int*)ei;
        int nz = 0;
        for (int k = 1; k < 2001; k += 2) nz |= p[k];
        g_is64 = (nz == 0) ? 1 : 0;
    }
}
__global__ void k_hist(const void* __restrict__ ei, const float* __restrict__ ew) {
    __shared__ unsigned smn, smx;
    if (threadIdx.x == 0) { smn = 0xFFFFFFFFu; smx = 0u; }
    __syncthreads();
    unsigned mn = 0xFFFFFFFFu, mx = 0u;
    for (int e = blockIdx.x * blockDim.x + threadIdx.x; e < EE; e += gridDim.x * blockDim.x) {
        unsigned b = __float_as_uint(ew[e]);
        mn = min(mn, b); mx = max(mx, b);
        atomicAdd(&g_bcnt[load_idx(ei, (size_t)EE + e)], 1);
    }
    #pragma unroll
    for (int o = 16; o; o >>= 1) {
        mn = min(mn, __shfl_xor_sync(0xFFFFFFFFu, mn, o));
        mx = max(mx, __shfl_xor_sync(0xFFFFFFFFu, mx, o));
    }
    if ((threadIdx.x & 31) == 0) { atomicMin(&smn, mn); atomicMax(&smx, mx); }
    __syncthreads();
    if (threadIdx.x == 0) { atomicMin(&g_mm[0], smn); atomicMax(&g_mm[1], smx); }
}
__global__ void k_scan1() {
    __shared__ int s[1024];
    int i = blockIdx.x * 1024 + threadIdx.x;
    int v = (i < NN) ? g_bcnt[i] : 0;
    s[threadIdx.x] = v;
    __syncthreads();
    for (int o = 1; o < 1024; o <<= 1) {
        int t = (threadIdx.x >= o) ? s[threadIdx.x - o] : 0;
        __syncthreads();
        s[threadIdx.x] += t;
        __syncthreads();
    }
    if (i < NN) g_boff[i] = s[threadIdx.x] - v;
    if (threadIdx.x == 1023) g_part[blockIdx.x] = s[1023];
}
__global__ void k_scan2() {
    __shared__ int s[64];
    int v = (threadIdx.x < NB1) ? g_part[threadIdx.x] : 0;
    s[threadIdx.x] = v;
    __syncthreads();
    for (int o = 1; o < 64; o <<= 1) {
        int t = (threadIdx.x >= o) ? s[threadIdx.x - o] : 0;
        __syncthreads();
        s[threadIdx.x] += t;
        __syncthreads();
    }
    if (threadIdx.x < NB1) g_part[threadIdx.x] = s[threadIdx.x] - v;
}
__global__ void k_scan3() {
    int i = blockIdx.x * blockDim.x + threadIdx.x;
    for (int j = i; j < NN; j += gridDim.x * blockDim.x)
        g_boff[j] += g_part[j >> 10];
    if (i == 0) g_boff[NN] = EE;
}
__global__ void k_reorder(const void* __restrict__ ei, const float* __restrict__ ew,
                          const void* __restrict__ et) {
    float mn = __uint_as_float(g_mm[0]);
    float mx = __uint_as_float(g_mm[1]);
    float sc = 1.0f / (mx - mn + 1e-8f);
    for (int e = blockIdx.x * blockDim.x + threadIdx.x; e < EE; e += gridDim.x * blockDim.x) {
        int src = load_idx(ei, e);
        int dst = load_idx(ei, (size_t)EE + e);
        int r   = load_idx(et, e);
        int cnt = g_boff[dst + 1] - g_boff[dst];
        int pos = g_boff[dst] + atomicAdd(&g_bcur[dst], 1);
        float coef = (ew[e] - mn) * sc / (float)max(cnt, 1);
        g_emeta[pos] = make_int2(src * NS + r, __float_as_int(coef));
    }
}

// ---------------------------------------------------------------------------
// mma.sync fp16 2-term GEMM, full-slot width per CTA.
// C[n, y*cstride + c] = sum_k A[n,k] * B_y[k,c], c in [0, BNT)
// A = a1 + a2 (fp16 hi/lo planes); B = b1 only. acc = a1*b1 + a2*b1.
// Grid (rowtiles, NS). A loaded ONCE per (tile, slot). 2 CTAs/SM.
// ---------------------------------------------------------------------------
#define PKA 136   // A smem row halves: 272B stride
#define SM_APL (128 * PKA * 2)          // 34816 per plane

template <int BNT>
__global__ void __launch_bounds__(256, 2)
tc_gemm(const __half* __restrict__ Ah, const __half* __restrict__ Al,
        const __half* __restrict__ Bh0,
        long strideB, int cstride,
        float* __restrict__ C, int ldc) {
    constexpr int PNB = BNT + 8;          // B smem row halves
    constexpr int SBB = PNB * 2;          // B row stride bytes
    constexpr int NP = BNT / 16;          // n16-pairs per k-step
    constexpr int CH = BNT / 8;           // 16B chunks per B k-row

    extern __shared__ char smem[];
    int tid = threadIdx.x, wid = tid >> 5, lane = tid & 31;
    int row0 = blockIdx.x * 128;
    const __half* Bh = Bh0 + (size_t)blockIdx.y * strideB;
    float* Cw = C + blockIdx.y * cstride;

    uint32_t uAh = smem_u32(smem);
    uint32_t uAl = uAh + SM_APL;
    uint32_t uBh = uAh + 2 * SM_APL;

    // ---- A: 128 rows x 256B per plane ----
    #pragma unroll
    for (int i = 0; i < 8; i++) {
        int c = tid + i * 256;
        int row = c >> 4, col = c & 15;
        int gr = row0 + row;
        uint32_t ok = (gr < NN) ? 16u : 0u;
        int grc = gr < NN ? gr : NN - 1;
        cp16(uAh + row * 272 + col * 16,
             (const char*)(Ah + (size_t)grc * FF) + col * 16, ok);
        cp16(uAl + row * 272 + col * 16,
             (const char*)(Al + (size_t)grc * FF) + col * 16, ok);
    }
    // ---- B: 128 k-rows x BNT*2 bytes, hi plane only ----
    #pragma unroll
    for (int i = 0; i < CH / 2; i++) {
        int c = tid + i * 256;
        int row = c / CH, col = c % CH;
        cp16(uBh + row * SBB + col * 16,
             (const char*)(Bh + (size_t)row * BNT) + col * 16, 16u);
    }
    asm volatile("cp.async.commit_group;" ::: "memory");
    asm volatile("cp.async.wait_group 0;" ::: "memory");
    __syncthreads();

    float acc[2 * NP][4];
    #pragma unroll
    for (int i = 0; i < 2 * NP; i++)
        #pragma unroll
        for (int q = 0; q < 4; q++) acc[i][q] = 0.f;

    int r = lane & 7, j = lane >> 3;
    int amrow = wid * 16 + r + 8 * (j & 1);
    int bncol0 = 8 * (j >> 1);

    #pragma unroll
    for (int ks = 0; ks < 8; ks++) {
        int k0 = ks * 16;
        uint32_t ah[4], al[4];
        int akcol = k0 + 8 * (j >> 1);
        ldsm_x4(ah[0], ah[1], ah[2], ah[3], uAh + (amrow * PKA + akcol) * 2);
        ldsm_x4(al[0], al[1], al[2], al[3], uAl + (amrow * PKA + akcol) * 2);
        int bkrow = k0 + r + 8 * (j & 1);
        #pragma unroll
        for (int p = 0; p < NP; p++) {
            uint32_t b0, b1, b2, b3;
            ldsm_x4t(b0, b1, b2, b3, uBh + bkrow * SBB + (p * 16 + bncol0) * 2);
            mma_f16(acc[2 * p + 0], ah, b0, b1);   // a1*b1
            mma_f16(acc[2 * p + 0], al, b0, b1);   // a2*b1
            mma_f16(acc[2 * p + 1], ah, b2, b3);
            mma_f16(acc[2 * p + 1], al, b2, b3);
        }
    }

    // ---- epilogue ----
    int orow = row0 + wid * 16 + lane / 4;
    int oc0 = 2 * (lane & 3);
    #pragma unroll
    for (int nt = 0; nt < 2 * NP; nt++) {
        int col = nt * 8 + oc0;
        if (orow < NN)
            *(float2*)&Cw[(size_t)orow * ldc + col] =
                make_float2(acc[nt][0], acc[nt][1]);
        if (orow + 8 < NN)
            *(float2*)&Cw[(size_t)(orow + 8) * ldc + col] =
                make_float2(acc[nt][2], acc[nt][3]);
    }
}

// ---------------------------------------------------------------------------
// Layer-1 aggregate: h = relu(Y1[root] + bias + msgs) -> fp16 planes (fused).
// ---------------------------------------------------------------------------
__global__ void k_agg1(const float* __restrict__ Y, const float* __restrict__ bias,
                       __half* __restrict__ hh, __half* __restrict__ hl) {
    int w = (blockIdx.x * blockDim.x + threadIdx.x) >> 5;
    int lane = threadIdx.x & 31;
    if (w >= NN) return;
    int s0 = g_boff[w], s1 = g_boff[w + 1];

    float4 rv = *(const float4*)(Y + ((size_t)w * NS + 8) * HH + lane * 4);
    float4 bv = *(const float4*)(bias + lane * 4);
    float a0 = rv.x + bv.x, a1 = rv.y + bv.y, a2 = rv.z + bv.z, a3 = rv.w + bv.w;

    for (int base = s0; base < s1; base += 32) {
        int idx = base + lane;
        int2 m = (idx < s1) ? g_emeta[idx] : make_int2(0, 0);
        int cnt = min(32, s1 - base);
        for (int jj = 0; jj < cnt; jj++) {
            int sr   = __shfl_sync(0xFFFFFFFFu, m.x, jj);
            float cf = __int_as_float(__shfl_sync(0xFFFFFFFFu, m.y, jj));
            float4 yv = *(const float4*)(Y + (size_t)sr * HH + lane * 4);
            a0 += cf * yv.x; a1 += cf * yv.y; a2 += cf * yv.z; a3 += cf * yv.w;
        }
    }
    float vs[4] = {fmaxf(a0, 0.f), fmaxf(a1, 0.f), fmaxf(a2, 0.f), fmaxf(a3, 0.f)};
    split4_store(vs, hh + (size_t)w * FF, hl + (size_t)w * FF, lane);
}

// ---------------------------------------------------------------------------
// Layer-2 aggregate: out = Y2[root] + bias + msgs (fp32).
// ---------------------------------------------------------------------------
__global__ void k_agg2(const float* __restrict__ Y, const float* __restrict__ bias,
                       float* __restrict__ out) {
    int w = (blockIdx.x * blockDim.x + threadIdx.x) >> 5;
    int lane = threadIdx.x & 31;
    if (w >= NN) return;
    int s0 = g_boff[w], s1 = g_boff[w + 1];

    float2 rv = *(const float2*)(Y + ((size_t)w * NS + 8) * OO + lane * 2);
    float a0 = rv.x + bias[lane * 2], a1 = rv.y + bias[lane * 2 + 1];

    for (int base = s0; base < s1; base += 32) {
        int idx = base + lane;
        int2 m = (idx < s1) ? g_emeta[idx] : make_int2(0, 0);
        int cnt = min(32, s1 - base);
        for (int jj = 0; jj < cnt; jj++) {
            int sr   = __shfl_sync(0xFFFFFFFFu, m.x, jj);
            float cf = __int_as_float(__shfl_sync(0xFFFFFFFFu, m.y, jj));
            float2 yv = *(const float2*)(Y + (size_t)sr * OO + lane * 2);
            a0 += cf * yv.x; a1 += cf * yv.y;
        }
    }
    *(float2*)&out[(size_t)w * OO + lane * 2] = make_float2(a0, a1);
}

// ---------------------------------------------------------------------------
// Launch
// ---------------------------------------------------------------------------
extern "C" void kernel_launch(void* const* d_in, const int* in_sizes, int n_in,
                              void* d_out, int out_size) {
    const float* x     = (const float*)d_in[0];
    const void*  ei    = d_in[1];
    const float* ew    = (const float*)d_in[2];
    const void*  et    = d_in[3];
    const float* W1    = (const float*)d_in[4];
    const float* root1 = (const float*)d_in[5];
    const float* bias1 = (const float*)d_in[6];
    const float* W2    = (const float*)d_in[7];
    const float* root2 = (const float*)d_in[8];
    const float* bias2 = (const float*)d_in[9];
    float* out = (float*)d_out;

    void *pY, *pAh, *pAl, *pWh;
    cudaGetSymbolAddress(&pY, g_Y);
    cudaGetSymbolAddress(&pAh, g_Ah);
    cudaGetSymbolAddress(&pAl, g_Al);
    cudaGetSymbolAddress(&pWh, g_Wh);
    const float* Yp = (const float*)pY;
    float*       Ym = (float*)pY;
    __half* Ah = (__half*)pAh;
    __half* Al = (__half*)pAl;
    __half* Wh = (__half*)pWh;

    const int GB = (NN + 127) / 128;   // 391 row tiles
    const int GA = (NN * 32 + 255) / 256;
    const int SMEM128 = 2 * SM_APL + 128 * (128 + 8) * 2;  // 104448
    const int SMEM64  = 2 * SM_APL + 128 * (64 + 8) * 2;   // 88064
    cudaFuncSetAttribute(tc_gemm<128>, cudaFuncAttributeMaxDynamicSharedMemorySize, SMEM128);
    cudaFuncSetAttribute(tc_gemm<64>,  cudaFuncAttributeMaxDynamicSharedMemorySize, SMEM64);

    k_zerodet<<<256, 256>>>(ei);                                     // 1
    k_split<<<(NN * FF / 4 + 255) / 256, 256>>>(x, Ah, Al, NN * FF / 4);          // 2
    k_splitW<<<((RR * FF * HH + FF * HH) / 4 + 255) / 256, 256>>>(   // 3
        W1, RR * FF * HH / 4, root1, FF * HH / 4, Wh);
    // Y1 (slots 0..8): grid (391, 9), BN=128 per CTA (A loaded once/slot)
    tc_gemm<128><<<dim3(GB, NS), 256, SMEM128>>>(                    // 4 (profiled)
        Ah, Al, Wh, (long)FF * HH, HH, Ym, NS * HH);

    k_hist<<<1024, 256>>>(ei, ew);                                   // 5
    k_scan1<<<NB1, 1024>>>();                                        // 6
    k_scan2<<<1, 64>>>();                                            // 7
    k_scan3<<<256, 256>>>();                                         // 8
    k_reorder<<<1024, 256>>>(ei, ew, et);                            // 9

    // h = relu(root + bias1 + agg) -> fp16 planes
    k_agg1<<<GA, 256>>>(Yp, bias1, Ah, Al);                          // 10

    k_splitW<<<((RR * HH * OO + HH * OO) / 4 + 255) / 256, 256>>>(   // 11
        W2, RR * HH * OO / 4, root2, HH * OO / 4, Wh);
    // Y2 (slots 0..8): grid (391, 9), BN=64
    tc_gemm<64><<<dim3(GB, NS), 256, SMEM64>>>(                      // 12
        Ah, Al, Wh, (long)HH * OO, OO, Ym, NS * OO);

    // out = root + bias2 + agg
    k_agg2<<<GA, 256>>>(Yp, bias2, out);                             // 13
}

// round 15
// speedup vs baseline: 1.2046x; 1.0332x over previous
#include <cuda_runtime.h>
#include <cuda_fp16.h>
#include <stdint.h>

// Problem constants
#define NN 50000
#define EE 600000
#define FF 128
#define HH 128
#define OO 64
#define RR 8
#define NS 9                       // 8 relations + root slot
#define NB1 ((NN + 1023) / 1024)   // 49 scan blocks

// ---------------------------------------------------------------------------
// Device scratch
// ---------------------------------------------------------------------------
__device__ float   g_Y[(size_t)NN * NS * HH];  // 230.4 MB projection buf
__device__ __half  g_Ah[(size_t)NN * FF];      // A hi plane (fp16)
__device__ __half  g_Al[(size_t)NN * FF];      // A lo plane (fp16 residual)
__device__ __half  g_Wh[NS * FF * HH];         // W hi (slots 0..8)
__device__ int     g_bcnt[NN];
__device__ int     g_bcur[NN];
__device__ int     g_boff[NN + 1];
__device__ int     g_part[64];
__device__ int2    g_emeta[EE];                // sorted: {src*9+r, coef}
__device__ unsigned g_mm[2];
__device__ int     g_is64;

// ---------------------------------------------------------------------------
// Helpers
// ---------------------------------------------------------------------------
__device__ __forceinline__ int load_idx(const void* p, size_t i) {
    return g_is64 ? (int)((const long long*)p)[i] : ((const int*)p)[i];
}
__device__ __forceinline__ uint32_t smem_u32(const void* p) {
    uint32_t a;
    asm("{ .reg .u64 t; cvta.to.shared.u64 t, %1; cvt.u32.u64 %0, t; }"
        : "=r"(a) : "l"(p));
    return a;
}
__device__ __forceinline__ void cp16(uint32_t d, const void* s, uint32_t nbytes) {
    asm volatile("cp.async.cg.shared.global [%0], [%1], 16, %2;"
                 :: "r"(d), "l"(s), "r"(nbytes) : "memory");
}
__device__ __forceinline__ void ldsm_x4(uint32_t& r0, uint32_t& r1,
                                        uint32_t& r2, uint32_t& r3, uint32_t a) {
    asm volatile("ldmatrix.sync.aligned.m8n8.x4.shared.b16 {%0,%1,%2,%3}, [%4];"
                 : "=r"(r0), "=r"(r1), "=r"(r2), "=r"(r3) : "r"(a));
}
__device__ __forceinline__ void ldsm_x4t(uint32_t& r0, uint32_t& r1,
                                         uint32_t& r2, uint32_t& r3, uint32_t a) {
    asm volatile("ldmatrix.sync.aligned.m8n8.x4.trans.shared.b16 {%0,%1,%2,%3}, [%4];"
                 : "=r"(r0), "=r"(r1), "=r"(r2), "=r"(r3) : "r"(a));
}
__device__ __forceinline__ void mma_f16(float* c, const uint32_t* a,
                                        uint32_t b0, uint32_t b1) {
    asm volatile(
        "mma.sync.aligned.m16n8k16.row.col.f32.f16.f16.f32 "
        "{%0,%1,%2,%3}, {%4,%5,%6,%7}, {%8,%9}, {%0,%1,%2,%3};"
        : "+f"(c[0]), "+f"(c[1]), "+f"(c[2]), "+f"(c[3])
        : "r"(a[0]), "r"(a[1]), "r"(a[2]), "r"(a[3]), "r"(b0), "r"(b1));
}
__device__ __forceinline__ void split1(float v, unsigned short& h, unsigned short& l) {
    __half b1 = __float2half_rn(v);
    __half b2 = __float2half_rn(v - __half2float(b1));
    h = __half_as_ushort(b1);
    l = __half_as_ushort(b2);
}
__device__ __forceinline__ void split4_store(const float* vs,
                                             __half* hi, __half* lo, int i) {
    unsigned short h[4], l[4];
    #pragma unroll
    for (int j = 0; j < 4; j++) split1(vs[j], h[j], l[j]);
    uint2 ph, pl;
    ph.x = (uint32_t)h[0] | ((uint32_t)h[1] << 16);
    ph.y = (uint32_t)h[2] | ((uint32_t)h[3] << 16);
    pl.x = (uint32_t)l[0] | ((uint32_t)l[1] << 16);
    pl.y = (uint32_t)l[2] | ((uint32_t)l[3] << 16);
    ((uint2*)hi)[i] = ph;
    ((uint2*)lo)[i] = pl;
}

// ---------------------------------------------------------------------------
// Split fp32 -> fp16 hi/lo planes (x / h). Hi-only variant for weights.
// ---------------------------------------------------------------------------
__global__ void k_split(const float* __restrict__ src,
                        __half* __restrict__ hi, __half* __restrict__ lo, int n4) {
    int i = blockIdx.x * blockDim.x + threadIdx.x;
    if (i >= n4) return;
    float4 v = ((const float4*)src)[i];
    float vs[4] = {v.x, v.y, v.z, v.w};
    split4_store(vs, hi, lo, i);
}

__global__ void k_splitW(const float* __restrict__ srcA, int n4a,
                         const float* __restrict__ srcB, int n4b,
                         __half* __restrict__ hi) {
    int i = blockIdx.x * blockDim.x + threadIdx.x;
    if (i >= n4a + n4b) return;
    float4 v = (i < n4a) ? ((const float4*)srcA)[i]
                         : ((const float4*)srcB)[i - n4a];
    unsigned short h0, h1, h2, h3, dummy;
    split1(v.x, h0, dummy); split1(v.y, h1, dummy);
    split1(v.z, h2, dummy); split1(v.w, h3, dummy);
    uint2 ph;
    ph.x = (uint32_t)h0 | ((uint32_t)h1 << 16);
    ph.y = (uint32_t)h2 | ((uint32_t)h3 << 16);
    ((uint2*)hi)[i] = ph;
}

// ---------------------------------------------------------------------------
// Edge preprocessing
// ---------------------------------------------------------------------------
__global__ void k_zerodet(const void* ei) {
    int i = blockIdx.x * blockDim.x + threadIdx.x;
    for (int j = i; j < NN; j += gridDim.x * blockDim.x) { g_bcnt[j] = 0; g_bcur[j] = 0; }
    if (i == 0) {
        g_mm[0] = 0xFFFFFFFFu; g_mm[1] = 0u;
        const int* p = (const int*)ei;
        int nz = 0;
        for (int k = 1; k < 2001; k += 2) nz |= p[k];
        g_is64 = (nz == 0) ? 1 : 0;
    }
}
__global__ void k_hist(const void* __restrict__ ei, const float* __restrict__ ew) {
    __shared__ unsigned smn, smx;
    if (threadIdx.x == 0) { smn = 0xFFFFFFFFu; smx = 0u; }
    __syncthreads();
    unsigned mn = 0xFFFFFFFFu, mx = 0u;
    for (int e = blockIdx.x * blockDim.x + threadIdx.x; e < EE; e += gridDim.x * blockDim.x) {
        unsigned b = __float_as_uint(ew[e]);
        mn = min(mn, b); mx = max(mx, b);
        atomicAdd(&g_bcnt[load_idx(ei, (size_t)EE + e)], 1);
    }
    #pragma unroll
    for (int o = 16; o; o >>= 1) {
        mn = min(mn, __shfl_xor_sync(0xFFFFFFFFu, mn, o));
        mx = max(mx, __shfl_xor_sync(0xFFFFFFFFu, mx, o));
    }
    if ((threadIdx.x & 31) == 0) { atomicMin(&smn, mn); atomicMax(&smx, mx); }
    __syncthreads();
    if (threadIdx.x == 0) { atomicMin(&g_mm[0], smn); atomicMax(&g_mm[1], smx); }
}
__global__ void k_scan1() {
    __shared__ int s[1024];
    int i = blockIdx.x * 1024 + threadIdx.x;
    int v = (i < NN) ? g_bcnt[i] : 0;
    s[threadIdx.x] = v;
    __syncthreads();
    for (int o = 1; o < 1024; o <<= 1) {
        int t = (threadIdx.x >= o) ? s[threadIdx.x - o] : 0;
        __syncthreads();
        s[threadIdx.x] += t;
        __syncthreads();
    }
    if (i < NN) g_boff[i] = s[threadIdx.x] - v;
    if (threadIdx.x == 1023) g_part[blockIdx.x] = s[1023];
}
__global__ void k_scan2() {
    __shared__ int s[64];
    int v = (threadIdx.x < NB1) ? g_part[threadIdx.x] : 0;
    s[threadIdx.x] = v;
    __syncthreads();
    for (int o = 1; o < 64; o <<= 1) {
        int t = (threadIdx.x >= o) ? s[threadIdx.x - o] : 0;
        __syncthreads();
        s[threadIdx.x] += t;
        __syncthreads();
    }
    if (threadIdx.x < NB1) g_part[threadIdx.x] = s[threadIdx.x] - v;
}
__global__ void k_scan3() {
    int i = blockIdx.x * blockDim.x + threadIdx.x;
    for (int j = i; j < NN; j += gridDim.x * blockDim.x)
        g_boff[j] += g_part[j >> 10];
    if (i == 0) g_boff[NN] = EE;
}
__global__ void k_reorder(const void* __restrict__ ei, const float* __restrict__ ew,
                          const void* __restrict__ et) {
    float mn = __uint_as_float(g_mm[0]);
    float mx = __uint_as_float(g_mm[1]);
    float sc = 1.0f / (mx - mn + 1e-8f);
    for (int e = blockIdx.x * blockDim.x + threadIdx.x; e < EE; e += gridDim.x * blockDim.x) {
        int src = load_idx(ei, e);
        int dst = load_idx(ei, (size_t)EE + e);
        int r   = load_idx(et, e);
        int cnt = g_boff[dst + 1] - g_boff[dst];
        int pos = g_boff[dst] + atomicAdd(&g_bcur[dst], 1);
        float coef = (ew[e] - mn) * sc / (float)max(cnt, 1);
        g_emeta[pos] = make_int2(src * NS + r, __float_as_int(coef));
    }
}

// ---------------------------------------------------------------------------
// mma.sync fp16 2-term GEMM, full-slot width per CTA (unchanged from R14).
// ---------------------------------------------------------------------------
#define PKA 136   // A smem row halves: 272B stride
#define SM_APL (128 * PKA * 2)          // 34816 per plane

template <int BNT>
__global__ void __launch_bounds__(256, 2)
tc_gemm(const __half* __restrict__ Ah, const __half* __restrict__ Al,
        const __half* __restrict__ Bh0,
        long strideB, int cstride,
        float* __restrict__ C, int ldc) {
    constexpr int PNB = BNT + 8;
    constexpr int SBB = PNB * 2;
    constexpr int NP = BNT / 16;
    constexpr int CH = BNT / 8;

    extern __shared__ char smem[];
    int tid = threadIdx.x, wid = tid >> 5, lane = tid & 31;
    int row0 = blockIdx.x * 128;
    const __half* Bh = Bh0 + (size_t)blockIdx.y * strideB;
    float* Cw = C + blockIdx.y * cstride;

    uint32_t uAh = smem_u32(smem);
    uint32_t uAl = uAh + SM_APL;
    uint32_t uBh = uAh + 2 * SM_APL;

    #pragma unroll
    for (int i = 0; i < 8; i++) {
        int c = tid + i * 256;
        int row = c >> 4, col = c & 15;
        int gr = row0 + row;
        uint32_t ok = (gr < NN) ? 16u : 0u;
        int grc = gr < NN ? gr : NN - 1;
        cp16(uAh + row * 272 + col * 16,
             (const char*)(Ah + (size_t)grc * FF) + col * 16, ok);
        cp16(uAl + row * 272 + col * 16,
             (const char*)(Al + (size_t)grc * FF) + col * 16, ok);
    }
    #pragma unroll
    for (int i = 0; i < CH / 2; i++) {
        int c = tid + i * 256;
        int row = c / CH, col = c % CH;
        cp16(uBh + row * SBB + col * 16,
             (const char*)(Bh + (size_t)row * BNT) + col * 16, 16u);
    }
    asm volatile("cp.async.commit_group;" ::: "memory");
    asm volatile("cp.async.wait_group 0;" ::: "memory");
    __syncthreads();

    float acc[2 * NP][4];
    #pragma unroll
    for (int i = 0; i < 2 * NP; i++)
        #pragma unroll
        for (int q = 0; q < 4; q++) acc[i][q] = 0.f;

    int r = lane & 7, j = lane >> 3;
    int amrow = wid * 16 + r + 8 * (j & 1);
    int bncol0 = 8 * (j >> 1);

    #pragma unroll
    for (int ks = 0; ks < 8; ks++) {
        int k0 = ks * 16;
        uint32_t ah[4], al[4];
        int akcol = k0 + 8 * (j >> 1);
        ldsm_x4(ah[0], ah[1], ah[2], ah[3], uAh + (amrow * PKA + akcol) * 2);
        ldsm_x4(al[0], al[1], al[2], al[3], uAl + (amrow * PKA + akcol) * 2);
        int bkrow = k0 + r + 8 * (j & 1);
        #pragma unroll
        for (int p = 0; p < NP; p++) {
            uint32_t b0, b1, b2, b3;
            ldsm_x4t(b0, b1, b2, b3, uBh + bkrow * SBB + (p * 16 + bncol0) * 2);
            mma_f16(acc[2 * p + 0], ah, b0, b1);
            mma_f16(acc[2 * p + 0], al, b0, b1);
            mma_f16(acc[2 * p + 1], ah, b2, b3);
            mma_f16(acc[2 * p + 1], al, b2, b3);
        }
    }

    int orow = row0 + wid * 16 + lane / 4;
    int oc0 = 2 * (lane & 3);
    #pragma unroll
    for (int nt = 0; nt < 2 * NP; nt++) {
        int col = nt * 8 + oc0;
        if (orow < NN)
            *(float2*)&Cw[(size_t)orow * ldc + col] =
                make_float2(acc[nt][0], acc[nt][1]);
        if (orow + 8 < NN)
            *(float2*)&Cw[(size_t)(orow + 8) * ldc + col] =
                make_float2(acc[nt][2], acc[nt][3]);
    }
}

// ---------------------------------------------------------------------------
// Layer-1 aggregate with MLP-8 software pipeline.
// h = relu(Y1[root] + bias + msgs) -> fp16 planes (fused split).
// Out-of-range lanes carry (src=0, coef=0) metas, so 8-groups run
// unconditionally: dummy loads hit row 0 (L2-hot), coef=0 nullifies them.
// ---------------------------------------------------------------------------
__global__ void k_agg1(const float* __restrict__ Y, const float* __restrict__ bias,
                       __half* __restrict__ hh, __half* __restrict__ hl) {
    int w = (blockIdx.x * blockDim.x + threadIdx.x) >> 5;
    int lane = threadIdx.x & 31;
    if (w >= NN) return;
    int s0 = g_boff[w], s1 = g_boff[w + 1];

    float4 rv = *(const float4*)(Y + ((size_t)w * NS + 8) * HH + lane * 4);
    float4 bv = *(const float4*)(bias + lane * 4);
    float a0 = rv.x + bv.x, a1 = rv.y + bv.y, a2 = rv.z + bv.z, a3 = rv.w + bv.w;

    for (int base = s0; base < s1; base += 32) {
        int idx = base + lane;
        int2 m = (idx < s1) ? g_emeta[idx] : make_int2(0, 0);
        int cnt = min(32, s1 - base);
        for (int jj = 0; jj < cnt; jj += 8) {
            int sr[8]; float cf[8];
            #pragma unroll
            for (int q = 0; q < 8; q++) {
                sr[q] = __shfl_sync(0xFFFFFFFFu, m.x, jj + q);
                cf[q] = __int_as_float(__shfl_sync(0xFFFFFFFFu, m.y, jj + q));
            }
            float4 yv[8];
            #pragma unroll
            for (int q = 0; q < 8; q++)
                yv[q] = *(const float4*)(Y + (size_t)sr[q] * HH + lane * 4);
            #pragma unroll
            for (int q = 0; q < 8; q++) {
                a0 += cf[q] * yv[q].x; a1 += cf[q] * yv[q].y;
                a2 += cf[q] * yv[q].z; a3 += cf[q] * yv[q].w;
            }
        }
    }
    float vs[4] = {fmaxf(a0, 0.f), fmaxf(a1, 0.f), fmaxf(a2, 0.f), fmaxf(a3, 0.f)};
    split4_store(vs, hh + (size_t)w * FF, hl + (size_t)w * FF, lane);
}

// ---------------------------------------------------------------------------
// Layer-2 aggregate with MLP-8 pipeline: out = Y2[root] + bias + msgs (fp32).
// ---------------------------------------------------------------------------
__global__ void k_agg2(const float* __restrict__ Y, const float* __restrict__ bias,
                       float* __restrict__ out) {
    int w = (blockIdx.x * blockDim.x + threadIdx.x) >> 5;
    int lane = threadIdx.x & 31;
    if (w >= NN) return;
    int s0 = g_boff[w], s1 = g_boff[w + 1];

    float2 rv = *(const float2*)(Y + ((size_t)w * NS + 8) * OO + lane * 2);
    float a0 = rv.x + bias[lane * 2], a1 = rv.y + bias[lane * 2 + 1];

    for (int base = s0; base < s1; base += 32) {
        int idx = base + lane;
        int2 m = (idx < s1) ? g_emeta[idx] : make_int2(0, 0);
        int cnt = min(32, s1 - base);
        for (int jj = 0; jj < cnt; jj += 8) {
            int sr[8]; float cf[8];
            #pragma unroll
            for (int q = 0; q < 8; q++) {
                sr[q] = __shfl_sync(0xFFFFFFFFu, m.x, jj + q);
                cf[q] = __int_as_float(__shfl_sync(0xFFFFFFFFu, m.y, jj + q));
            }
            float2 yv[8];
            #pragma unroll
            for (int q = 0; q < 8; q++)
                yv[q] = *(const float2*)(Y + (size_t)sr[q] * OO + lane * 2);
            #pragma unroll
            for (int q = 0; q < 8; q++) {
                a0 += cf[q] * yv[q].x; a1 += cf[q] * yv[q].y;
            }
        }
    }
    *(float2*)&out[(size_t)w * OO + lane * 2] = make_float2(a0, a1);
}

// ---------------------------------------------------------------------------
// Launch
// ---------------------------------------------------------------------------
extern "C" void kernel_launch(void* const* d_in, const int* in_sizes, int n_in,
                              void* d_out, int out_size) {
    const float* x     = (const float*)d_in[0];
    const void*  ei    = d_in[1];
    const float* ew    = (const float*)d_in[2];
    const void*  et    = d_in[3];
    const float* W1    = (const float*)d_in[4];
    const float* root1 = (const float*)d_in[5];
    const float* bias1 = (const float*)d_in[6];
    const float* W2    = (const float*)d_in[7];
    const float* root2 = (const float*)d_in[8];
    const float* bias2 = (const float*)d_in[9];
    float* out = (float*)d_out;

    void *pY, *pAh, *pAl, *pWh;
    cudaGetSymbolAddress(&pY, g_Y);
    cudaGetSymbolAddress(&pAh, g_Ah);
    cudaGetSymbolAddress(&pAl, g_Al);
    cudaGetSymbolAddress(&pWh, g_Wh);
    const float* Yp = (const float*)pY;
    float*       Ym = (float*)pY;
    __half* Ah = (__half*)pAh;
    __half* Al = (__half*)pAl;
    __half* Wh = (__half*)pWh;

    const int GB = (NN + 127) / 128;   // 391 row tiles
    const int GA = (NN * 32 + 255) / 256;
    const int SMEM128 = 2 * SM_APL + 128 * (128 + 8) * 2;  // 104448
    const int SMEM64  = 2 * SM_APL + 128 * (64 + 8) * 2;   // 88064
    cudaFuncSetAttribute(tc_gemm<128>, cudaFuncAttributeMaxDynamicSharedMemorySize, SMEM128);
    cudaFuncSetAttribute(tc_gemm<64>,  cudaFuncAttributeMaxDynamicSharedMemorySize, SMEM64);

    k_zerodet<<<256, 256>>>(ei);                                     // 1
    k_split<<<(NN * FF / 4 + 255) / 256, 256>>>(x, Ah, Al, NN * FF / 4);          // 2
    k_splitW<<<((RR * FF * HH + FF * HH) / 4 + 255) / 256, 256>>>(   // 3
        W1, RR * FF * HH / 4, root1, FF * HH / 4, Wh);
    // Y1 (slots 0..8): grid (391, 9), BN=128 per CTA
    tc_gemm<128><<<dim3(GB, NS), 256, SMEM128>>>(                    // 4 (profiled)
        Ah, Al, Wh, (long)FF * HH, HH, Ym, NS * HH);

    k_hist<<<1024, 256>>>(ei, ew);                                   // 5
    k_scan1<<<NB1, 1024>>>();                                        // 6
    k_scan2<<<1, 64>>>();                                            // 7
    k_scan3<<<256, 256>>>();                                         // 8
    k_reorder<<<1024, 256>>>(ei, ew, et);                            // 9

    // h = relu(root + bias1 + agg) -> fp16 planes
    k_agg1<<<GA, 256>>>(Yp, bias1, Ah, Al);                          // 10

    k_splitW<<<((RR * HH * OO + HH * OO) / 4 + 255) / 256, 256>>>(   // 11
        W2, RR * HH * OO / 4, root2, HH * OO / 4, Wh);
    // Y2 (slots 0..8): grid (391, 9), BN=64
    tc_gemm<64><<<dim3(GB, NS), 256, SMEM64>>>(                      // 12
        Ah, Al, Wh, (long)HH * OO, OO, Ym, NS * OO);

    // out = root + bias2 + agg
    k_agg2<<<GA, 256>>>(Yp, bias2, out);                             // 13
}

// round 16
// speedup vs baseline: 1.3445x; 1.1161x over previous
#include <cuda_runtime.h>
#include <cuda_fp16.h>
#include <stdint.h>

// Problem constants
#define NN 50000
#define EE 600000
#define FF 128
#define HH 128
#define OO 64
#define RR 8
#define NS 9                       // 8 relations + root slot
#define NB1 ((NN + 1023) / 1024)   // 49 scan blocks

// ---------------------------------------------------------------------------
// Device scratch
// ---------------------------------------------------------------------------
__device__ __half  g_Yh[(size_t)NN * RR * HH];  // 102.4 MB message buf (fp16)
__device__ float   g_R[(size_t)NN * HH];        // 25.6 MB root-term buf (fp32)
__device__ __half  g_Ah[(size_t)NN * FF];       // A hi plane (fp16)
__device__ __half  g_Al[(size_t)NN * FF];       // A lo plane (fp16 residual)
__device__ __half  g_Wh[NS * FF * HH];          // W hi (slots 0..8)
__device__ int     g_bcnt[NN];
__device__ int     g_bcur[NN];
__device__ int     g_boff[NN + 1];
__device__ int     g_part[64];
__device__ int2    g_emeta[EE];                 // sorted: {src*8+r, coef}
__device__ unsigned g_mm[2];
__device__ int     g_is64;

// ---------------------------------------------------------------------------
// Helpers
// ---------------------------------------------------------------------------
__device__ __forceinline__ int load_idx(const void* p, size_t i) {
    return g_is64 ? (int)((const long long*)p)[i] : ((const int*)p)[i];
}
__device__ __forceinline__ uint32_t smem_u32(const void* p) {
    uint32_t a;
    asm("{ .reg .u64 t; cvta.to.shared.u64 t, %1; cvt.u32.u64 %0, t; }"
        : "=r"(a) : "l"(p));
    return a;
}
__device__ __forceinline__ void cp16(uint32_t d, const void* s, uint32_t nbytes) {
    asm volatile("cp.async.cg.shared.global [%0], [%1], 16, %2;"
                 :: "r"(d), "l"(s), "r"(nbytes) : "memory");
}
__device__ __forceinline__ void ldsm_x4(uint32_t& r0, uint32_t& r1,
                                        uint32_t& r2, uint32_t& r3, uint32_t a) {
    asm volatile("ldmatrix.sync.aligned.m8n8.x4.shared.b16 {%0,%1,%2,%3}, [%4];"
                 : "=r"(r0), "=r"(r1), "=r"(r2), "=r"(r3) : "r"(a));
}
__device__ __forceinline__ void ldsm_x4t(uint32_t& r0, uint32_t& r1,
                                         uint32_t& r2, uint32_t& r3, uint32_t a) {
    asm volatile("ldmatrix.sync.aligned.m8n8.x4.trans.shared.b16 {%0,%1,%2,%3}, [%4];"
                 : "=r"(r0), "=r"(r1), "=r"(r2), "=r"(r3) : "r"(a));
}
__device__ __forceinline__ void mma_f16(float* c, const uint32_t* a,
                                        uint32_t b0, uint32_t b1) {
    asm volatile(
        "mma.sync.aligned.m16n8k16.row.col.f32.f16.f16.f32 "
        "{%0,%1,%2,%3}, {%4,%5,%6,%7}, {%8,%9}, {%0,%1,%2,%3};"
        : "+f"(c[0]), "+f"(c[1]), "+f"(c[2]), "+f"(c[3])
        : "r"(a[0]), "r"(a[1]), "r"(a[2]), "r"(a[3]), "r"(b0), "r"(b1));
}
__device__ __forceinline__ void split1(float v, unsigned short& h, unsigned short& l) {
    __half b1 = __float2half_rn(v);
    __half b2 = __float2half_rn(v - __half2float(b1));
    h = __half_as_ushort(b1);
    l = __half_as_ushort(b2);
}
__device__ __forceinline__ void split4_store(const float* vs,
                                             __half* hi, __half* lo, int i) {
    unsigned short h[4], l[4];
    #pragma unroll
    for (int j = 0; j < 4; j++) split1(vs[j], h[j], l[j]);
    uint2 ph, pl;
    ph.x = (uint32_t)h[0] | ((uint32_t)h[1] << 16);
    ph.y = (uint32_t)h[2] | ((uint32_t)h[3] << 16);
    pl.x = (uint32_t)l[0] | ((uint32_t)l[1] << 16);
    pl.y = (uint32_t)l[2] | ((uint32_t)l[3] << 16);
    ((uint2*)hi)[i] = ph;
    ((uint2*)lo)[i] = pl;
}

// ---------------------------------------------------------------------------
// Split fp32 -> fp16 hi/lo planes (x / h). Hi-only variant for weights.
// ---------------------------------------------------------------------------
__global__ void k_split(const float* __restrict__ src,
                        __half* __restrict__ hi, __half* __restrict__ lo, int n4) {
    int i = blockIdx.x * blockDim.x + threadIdx.x;
    if (i >= n4) return;
    float4 v = ((const float4*)src)[i];
    float vs[4] = {v.x, v.y, v.z, v.w};
    split4_store(vs, hi, lo, i);
}

__global__ void k_splitW(const float* __restrict__ srcA, int n4a,
                         const float* __restrict__ srcB, int n4b,
                         __half* __restrict__ hi) {
    int i = blockIdx.x * blockDim.x + threadIdx.x;
    if (i >= n4a + n4b) return;
    float4 v = (i < n4a) ? ((const float4*)srcA)[i]
                         : ((const float4*)srcB)[i - n4a];
    unsigned short h0, h1, h2, h3, dummy;
    split1(v.x, h0, dummy); split1(v.y, h1, dummy);
    split1(v.z, h2, dummy); split1(v.w, h3, dummy);
    uint2 ph;
    ph.x = (uint32_t)h0 | ((uint32_t)h1 << 16);
    ph.y = (uint32_t)h2 | ((uint32_t)h3 << 16);
    ((uint2*)hi)[i] = ph;
}

// ---------------------------------------------------------------------------
// Edge preprocessing
// ---------------------------------------------------------------------------
__global__ void k_zerodet(const void* ei) {
    int i = blockIdx.x * blockDim.x + threadIdx.x;
    for (int j = i; j < NN; j += gridDim.x * blockDim.x) { g_bcnt[j] = 0; g_bcur[j] = 0; }
    if (i == 0) {
        g_mm[0] = 0xFFFFFFFFu; g_mm[1] = 0u;
        const int* p = (const int*)ei;
        int nz = 0;
        for (int k = 1; k < 2001; k += 2) nz |= p[k];
        g_is64 = (nz == 0) ? 1 : 0;
    }
}
__global__ void k_hist(const void* __restrict__ ei, const float* __restrict__ ew) {
    __shared__ unsigned smn, smx;
    if (threadIdx.x == 0) { smn = 0xFFFFFFFFu; smx = 0u; }
    __syncthreads();
    unsigned mn = 0xFFFFFFFFu, mx = 0u;
    for (int e = blockIdx.x * blockDim.x + threadIdx.x; e < EE; e += gridDim.x * blockDim.x) {
        unsigned b = __float_as_uint(ew[e]);
        mn = min(mn, b); mx = max(mx, b);
        atomicAdd(&g_bcnt[load_idx(ei, (size_t)EE + e)], 1);
    }
    #pragma unroll
    for (int o = 16; o; o >>= 1) {
        mn = min(mn, __shfl_xor_sync(0xFFFFFFFFu, mn, o));
        mx = max(mx, __shfl_xor_sync(0xFFFFFFFFu, mx, o));
    }
    if ((threadIdx.x & 31) == 0) { atomicMin(&smn, mn); atomicMax(&smx, mx); }
    __syncthreads();
    if (threadIdx.x == 0) { atomicMin(&g_mm[0], smn); atomicMax(&g_mm[1], smx); }
}
__global__ void k_scan1() {
    __shared__ int s[1024];
    int i = blockIdx.x * 1024 + threadIdx.x;
    int v = (i < NN) ? g_bcnt[i] : 0;
    s[threadIdx.x] = v;
    __syncthreads();
    for (int o = 1; o < 1024; o <<= 1) {
        int t = (threadIdx.x >= o) ? s[threadIdx.x - o] : 0;
        __syncthreads();
        s[threadIdx.x] += t;
        __syncthreads();
    }
    if (i < NN) g_boff[i] = s[threadIdx.x] - v;
    if (threadIdx.x == 1023) g_part[blockIdx.x] = s[1023];
}
__global__ void k_scan2() {
    __shared__ int s[64];
    int v = (threadIdx.x < NB1) ? g_part[threadIdx.x] : 0;
    s[threadIdx.x] = v;
    __syncthreads();
    for (int o = 1; o < 64; o <<= 1) {
        int t = (threadIdx.x >= o) ? s[threadIdx.x - o] : 0;
        __syncthreads();
        s[threadIdx.x] += t;
        __syncthreads();
    }
    if (threadIdx.x < NB1) g_part[threadIdx.x] = s[threadIdx.x] - v;
}
__global__ void k_scan3() {
    int i = blockIdx.x * blockDim.x + threadIdx.x;
    for (int j = i; j < NN; j += gridDim.x * blockDim.x)
        g_boff[j] += g_part[j >> 10];
    if (i == 0) g_boff[NN] = EE;
}
__global__ void k_reorder(const void* __restrict__ ei, const float* __restrict__ ew,
                          const void* __restrict__ et) {
    float mn = __uint_as_float(g_mm[0]);
    float mx = __uint_as_float(g_mm[1]);
    float sc = 1.0f / (mx - mn + 1e-8f);
    for (int e = blockIdx.x * blockDim.x + threadIdx.x; e < EE; e += gridDim.x * blockDim.x) {
        int src = load_idx(ei, e);
        int dst = load_idx(ei, (size_t)EE + e);
        int r   = load_idx(et, e);
        int cnt = g_boff[dst + 1] - g_boff[dst];
        int pos = g_boff[dst] + atomicAdd(&g_bcur[dst], 1);
        float coef = (ew[e] - mn) * sc / (float)max(cnt, 1);
        g_emeta[pos] = make_int2(src * RR + r, __float_as_int(coef));
    }
}

// ---------------------------------------------------------------------------
// mma.sync fp16 2-term GEMM, full-slot width per CTA.
// Slots 0..7 (relations): epilogue converts acc -> fp16 into Yh
//   (layout Yh[n][r][0..BNT), row stride RR*BNT halves).
// Slot 8 (root): epilogue writes fp32 into R (row stride BNT floats).
// ---------------------------------------------------------------------------
#define PKA 136   // A smem row halves: 272B stride
#define SM_APL (128 * PKA * 2)          // 34816 per plane

template <int BNT>
__global__ void __launch_bounds__(256, 2)
tc_gemm(const __half* __restrict__ Ah, const __half* __restrict__ Al,
        const __half* __restrict__ Bh0, long strideB,
        __half* __restrict__ Yh, float* __restrict__ R) {
    constexpr int PNB = BNT + 8;
    constexpr int SBB = PNB * 2;
    constexpr int NP = BNT / 16;
    constexpr int CH = BNT / 8;

    extern __shared__ char smem[];
    int tid = threadIdx.x, wid = tid >> 5, lane = tid & 31;
    int row0 = blockIdx.x * 128;
    const __half* Bh = Bh0 + (size_t)blockIdx.y * strideB;

    uint32_t uAh = smem_u32(smem);
    uint32_t uAl = uAh + SM_APL;
    uint32_t uBh = uAh + 2 * SM_APL;

    #pragma unroll
    for (int i = 0; i < 8; i++) {
        int c = tid + i * 256;
        int row = c >> 4, col = c & 15;
        int gr = row0 + row;
        uint32_t ok = (gr < NN) ? 16u : 0u;
        int grc = gr < NN ? gr : NN - 1;
        cp16(uAh + row * 272 + col * 16,
             (const char*)(Ah + (size_t)grc * FF) + col * 16, ok);
        cp16(uAl + row * 272 + col * 16,
             (const char*)(Al + (size_t)grc * FF) + col * 16, ok);
    }
    #pragma unroll
    for (int i = 0; i < CH / 2; i++) {
        int c = tid + i * 256;
        int row = c / CH, col = c % CH;
        cp16(uBh + row * SBB + col * 16,
             (const char*)(Bh + (size_t)row * BNT) + col * 16, 16u);
    }
    asm volatile("cp.async.commit_group;" ::: "memory");
    asm volatile("cp.async.wait_group 0;" ::: "memory");
    __syncthreads();

    float acc[2 * NP][4];
    #pragma unroll
    for (int i = 0; i < 2 * NP; i++)
        #pragma unroll
        for (int q = 0; q < 4; q++) acc[i][q] = 0.f;

    int r = lane & 7, j = lane >> 3;
    int amrow = wid * 16 + r + 8 * (j & 1);
    int bncol0 = 8 * (j >> 1);

    #pragma unroll
    for (int ks = 0; ks < 8; ks++) {
        int k0 = ks * 16;
        uint32_t ah[4], al[4];
        int akcol = k0 + 8 * (j >> 1);
        ldsm_x4(ah[0], ah[1], ah[2], ah[3], uAh + (amrow * PKA + akcol) * 2);
        ldsm_x4(al[0], al[1], al[2], al[3], uAl + (amrow * PKA + akcol) * 2);
        int bkrow = k0 + r + 8 * (j & 1);
        #pragma unroll
        for (int p = 0; p < NP; p++) {
            uint32_t b0, b1, b2, b3;
            ldsm_x4t(b0, b1, b2, b3, uBh + bkrow * SBB + (p * 16 + bncol0) * 2);
            mma_f16(acc[2 * p + 0], ah, b0, b1);
            mma_f16(acc[2 * p + 0], al, b0, b1);
            mma_f16(acc[2 * p + 1], ah, b2, b3);
            mma_f16(acc[2 * p + 1], al, b2, b3);
        }
    }

    int orow = row0 + wid * 16 + lane / 4;
    int oc0 = 2 * (lane & 3);
    if (blockIdx.y < RR) {
        // message slot -> fp16 Yh
        __half* base = Yh + (size_t)blockIdx.y * BNT;
        #pragma unroll
        for (int nt = 0; nt < 2 * NP; nt++) {
            int col = nt * 8 + oc0;
            if (orow < NN)
                *(__half2*)&base[(size_t)orow * (RR * BNT) + col] =
                    __floats2half2_rn(acc[nt][0], acc[nt][1]);
            if (orow + 8 < NN)
                *(__half2*)&base[(size_t)(orow + 8) * (RR * BNT) + col] =
                    __floats2half2_rn(acc[nt][2], acc[nt][3]);
        }
    } else {
        // root slot -> fp32 R
        #pragma unroll
        for (int nt = 0; nt < 2 * NP; nt++) {
            int col = nt * 8 + oc0;
            if (orow < NN)
                *(float2*)&R[(size_t)orow * BNT + col] =
                    make_float2(acc[nt][0], acc[nt][1]);
            if (orow + 8 < NN)
                *(float2*)&R[(size_t)(orow + 8) * BNT + col] =
                    make_float2(acc[nt][2], acc[nt][3]);
        }
    }
}

// ---------------------------------------------------------------------------
// Layer-1 aggregate, MLP-8, fp16 message gather.
// h = relu(R + bias + sum coef*Yh[src*8+r]) -> fp16 planes (fused split).
// ---------------------------------------------------------------------------
__global__ void k_agg1(const __half* __restrict__ Yh, const float* __restrict__ R,
                       const float* __restrict__ bias,
                       __half* __restrict__ hh, __half* __restrict__ hl) {
    int w = (blockIdx.x * blockDim.x + threadIdx.x) >> 5;
    int lane = threadIdx.x & 31;
    if (w >= NN) return;
    int s0 = g_boff[w], s1 = g_boff[w + 1];

    float4 rv = *(const float4*)(R + (size_t)w * HH + lane * 4);
    float4 bv = *(const float4*)(bias + lane * 4);
    float a0 = rv.x + bv.x, a1 = rv.y + bv.y, a2 = rv.z + bv.z, a3 = rv.w + bv.w;

    for (int base = s0; base < s1; base += 32) {
        int idx = base + lane;
        int2 m = (idx < s1) ? g_emeta[idx] : make_int2(0, 0);
        int cnt = min(32, s1 - base);
        for (int jj = 0; jj < cnt; jj += 8) {
            int sr[8]; float cf[8];
            #pragma unroll
            for (int q = 0; q < 8; q++) {
                sr[q] = __shfl_sync(0xFFFFFFFFu, m.x, jj + q);
                cf[q] = __int_as_float(__shfl_sync(0xFFFFFFFFu, m.y, jj + q));
            }
            uint2 raw[8];
            #pragma unroll
            for (int q = 0; q < 8; q++)
                raw[q] = *(const uint2*)(Yh + (size_t)sr[q] * HH + lane * 4);
            #pragma unroll
            for (int q = 0; q < 8; q++) {
                float2 f0 = __half22float2(*(__half2*)&raw[q].x);
                float2 f1 = __half22float2(*(__half2*)&raw[q].y);
                a0 += cf[q] * f0.x; a1 += cf[q] * f0.y;
                a2 += cf[q] * f1.x; a3 += cf[q] * f1.y;
            }
        }
    }
    float vs[4] = {fmaxf(a0, 0.f), fmaxf(a1, 0.f), fmaxf(a2, 0.f), fmaxf(a3, 0.f)};
    split4_store(vs, hh + (size_t)w * FF, hl + (size_t)w * FF, lane);
}

// ---------------------------------------------------------------------------
// Layer-2 aggregate, MLP-8, fp16 message gather: out = R + bias + msgs (fp32).
// ---------------------------------------------------------------------------
__global__ void k_agg2(const __half* __restrict__ Yh, const float* __restrict__ R,
                       const float* __restrict__ bias, float* __restrict__ out) {
    int w = (blockIdx.x * blockDim.x + threadIdx.x) >> 5;
    int lane = threadIdx.x & 31;
    if (w >= NN) return;
    int s0 = g_boff[w], s1 = g_boff[w + 1];

    float2 rv = *(const float2*)(R + (size_t)w * OO + lane * 2);
    float a0 = rv.x + bias[lane * 2], a1 = rv.y + bias[lane * 2 + 1];

    for (int base = s0; base < s1; base += 32) {
        int idx = base + lane;
        int2 m = (idx < s1) ? g_emeta[idx] : make_int2(0, 0);
        int cnt = min(32, s1 - base);
        for (int jj = 0; jj < cnt; jj += 8) {
            int sr[8]; float cf[8];
            #pragma unroll
            for (int q = 0; q < 8; q++) {
                sr[q] = __shfl_sync(0xFFFFFFFFu, m.x, jj + q);
                cf[q] = __int_as_float(__shfl_sync(0xFFFFFFFFu, m.y, jj + q));
            }
            uint32_t raw[8];
            #pragma unroll
            for (int q = 0; q < 8; q++)
                raw[q] = *(const uint32_t*)(Yh + (size_t)sr[q] * OO + lane * 2);
            #pragma unroll
            for (int q = 0; q < 8; q++) {
                float2 f0 = __half22float2(*(__half2*)&raw[q]);
                a0 += cf[q] * f0.x; a1 += cf[q] * f0.y;
            }
        }
    }
    *(float2*)&out[(size_t)w * OO + lane * 2] = make_float2(a0, a1);
}

// ---------------------------------------------------------------------------
// Launch
// ---------------------------------------------------------------------------
extern "C" void kernel_launch(void* const* d_in, const int* in_sizes, int n_in,
                              void* d_out, int out_size) {
    const float* x     = (const float*)d_in[0];
    const void*  ei    = d_in[1];
    const float* ew    = (const float*)d_in[2];
    const void*  et    = d_in[3];
    const float* W1    = (const float*)d_in[4];
    const float* root1 = (const float*)d_in[5];
    const float* bias1 = (const float*)d_in[6];
    const float* W2    = (const float*)d_in[7];
    const float* root2 = (const float*)d_in[8];
    const float* bias2 = (const float*)d_in[9];
    float* out = (float*)d_out;

    void *pYh, *pR, *pAh, *pAl, *pWh;
    cudaGetSymbolAddress(&pYh, g_Yh);
    cudaGetSymbolAddress(&pR, g_R);
    cudaGetSymbolAddress(&pAh, g_Ah);
    cudaGetSymbolAddress(&pAl, g_Al);
    cudaGetSymbolAddress(&pWh, g_Wh);
    __half* Yh = (__half*)pYh;
    float*  Rp = (float*)pR;
    __half* Ah = (__half*)pAh;
    __half* Al = (__half*)pAl;
    __half* Wh = (__half*)pWh;

    const int GB = (NN + 127) / 128;   // 391 row tiles
    const int GA = (NN * 32 + 255) / 256;
    const int SMEM128 = 2 * SM_APL + 128 * (128 + 8) * 2;  // 104448
    const int SMEM64  = 2 * SM_APL + 128 * (64 + 8) * 2;   // 88064
    cudaFuncSetAttribute(tc_gemm<128>, cudaFuncAttributeMaxDynamicSharedMemorySize, SMEM128);
    cudaFuncSetAttribute(tc_gemm<64>,  cudaFuncAttributeMaxDynamicSharedMemorySize, SMEM64);

    k_zerodet<<<256, 256>>>(ei);                                     // 1
    k_split<<<(NN * FF / 4 + 255) / 256, 256>>>(x, Ah, Al, NN * FF / 4);          // 2
    k_splitW<<<((RR * FF * HH + FF * HH) / 4 + 255) / 256, 256>>>(   // 3
        W1, RR * FF * HH / 4, root1, FF * HH / 4, Wh);
    // Y1 (slots 0..7 fp16 msgs, slot 8 fp32 root): grid (391, 9)
    tc_gemm<128><<<dim3(GB, NS), 256, SMEM128>>>(                    // 4 (profiled)
        Ah, Al, Wh, (long)FF * HH, Yh, Rp);

    k_hist<<<1024, 256>>>(ei, ew);                                   // 5
    k_scan1<<<NB1, 1024>>>();                                        // 6
    k_scan2<<<1, 64>>>();                                            // 7
    k_scan3<<<256, 256>>>();                                         // 8
    k_reorder<<<1024, 256>>>(ei, ew, et);                            // 9

    // h = relu(root + bias1 + agg) -> fp16 planes
    k_agg1<<<GA, 256>>>(Yh, Rp, bias1, Ah, Al);                      // 10

    k_splitW<<<((RR * HH * OO + HH * OO) / 4 + 255) / 256, 256>>>(   // 11
        W2, RR * HH * OO / 4, root2, HH * OO / 4, Wh);
    // Y2: grid (391, 9), BN=64
    tc_gemm<64><<<dim3(GB, NS), 256, SMEM64>>>(                      // 12
        Ah, Al, Wh, (long)HH * OO, Yh, Rp);

    // out = root + bias2 + agg
    k_agg2<<<GA, 256>>>(Yh, Rp, bias2, out);                         // 13
}

// round 17
// speedup vs baseline: 1.3650x; 1.0153x over previous
#include <cuda_runtime.h>
#include <cuda_fp16.h>
#include <stdint.h>

// Problem constants
#define NN 50000
#define EE 600000
#define FF 128
#define HH 128
#define OO 64
#define RR 8
#define NS 9                       // 8 relations + root slot
#define NB1 ((NN + 1023) / 1024)   // 49 scan blocks

// ---------------------------------------------------------------------------
// Device scratch
// ---------------------------------------------------------------------------
__device__ __half  g_Yh[(size_t)NN * RR * HH];  // 102.4 MB message buf (fp16)
__device__ float   g_R[(size_t)NN * HH];        // 25.6 MB root-term buf (fp32)
__device__ __half  g_Ah[(size_t)NN * FF];       // A hi plane (fp16)
__device__ __half  g_Al[(size_t)NN * FF];       // A lo plane (fp16 residual)
__device__ __half  g_Wh[NS * FF * HH];          // W hi (slots 0..8)
__device__ int     g_bcnt[NN];
__device__ int     g_bcur[NN];
__device__ int     g_boff[NN + 1];
__device__ int     g_part[64];
__device__ int2    g_emeta[EE];                 // sorted: {src*8+r, coef}
__device__ unsigned g_mm[2];
__device__ int     g_is64;

// ---------------------------------------------------------------------------
// Helpers
// ---------------------------------------------------------------------------
__device__ __forceinline__ int load_idx(const void* p, size_t i) {
    return g_is64 ? (int)((const long long*)p)[i] : ((const int*)p)[i];
}
__device__ __forceinline__ uint32_t smem_u32(const void* p) {
    uint32_t a;
    asm("{ .reg .u64 t; cvta.to.shared.u64 t, %1; cvt.u32.u64 %0, t; }"
        : "=r"(a) : "l"(p));
    return a;
}
__device__ __forceinline__ void cp16(uint32_t d, const void* s, uint32_t nbytes) {
    asm volatile("cp.async.cg.shared.global [%0], [%1], 16, %2;"
                 :: "r"(d), "l"(s), "r"(nbytes) : "memory");
}
__device__ __forceinline__ void ldsm_x4(uint32_t& r0, uint32_t& r1,
                                        uint32_t& r2, uint32_t& r3, uint32_t a) {
    asm volatile("ldmatrix.sync.aligned.m8n8.x4.shared.b16 {%0,%1,%2,%3}, [%4];"
                 : "=r"(r0), "=r"(r1), "=r"(r2), "=r"(r3) : "r"(a));
}
__device__ __forceinline__ void ldsm_x4t(uint32_t& r0, uint32_t& r1,
                                         uint32_t& r2, uint32_t& r3, uint32_t a) {
    asm volatile("ldmatrix.sync.aligned.m8n8.x4.trans.shared.b16 {%0,%1,%2,%3}, [%4];"
                 : "=r"(r0), "=r"(r1), "=r"(r2), "=r"(r3) : "r"(a));
}
__device__ __forceinline__ void mma_f16(float* c, const uint32_t* a,
                                        uint32_t b0, uint32_t b1) {
    asm volatile(
        "mma.sync.aligned.m16n8k16.row.col.f32.f16.f16.f32 "
        "{%0,%1,%2,%3}, {%4,%5,%6,%7}, {%8,%9}, {%0,%1,%2,%3};"
        : "+f"(c[0]), "+f"(c[1]), "+f"(c[2]), "+f"(c[3])
        : "r"(a[0]), "r"(a[1]), "r"(a[2]), "r"(a[3]), "r"(b0), "r"(b1));
}
__device__ __forceinline__ void split1(float v, unsigned short& h, unsigned short& l) {
    __half b1 = __float2half_rn(v);
    __half b2 = __float2half_rn(v - __half2float(b1));
    h = __half_as_ushort(b1);
    l = __half_as_ushort(b2);
}
__device__ __forceinline__ void split4_store(const float* vs,
                                             __half* hi, __half* lo, int i) {
    unsigned short h[4], l[4];
    #pragma unroll
    for (int j = 0; j < 4; j++) split1(vs[j], h[j], l[j]);
    uint2 ph, pl;
    ph.x = (uint32_t)h[0] | ((uint32_t)h[1] << 16);
    ph.y = (uint32_t)h[2] | ((uint32_t)h[3] << 16);
    pl.x = (uint32_t)l[0] | ((uint32_t)l[1] << 16);
    pl.y = (uint32_t)l[2] | ((uint32_t)l[3] << 16);
    ((uint2*)hi)[i] = ph;
    ((uint2*)lo)[i] = pl;
}

// ---------------------------------------------------------------------------
// Split fp32 -> fp16 hi/lo planes (x / h). Hi-only variant for weights.
// ---------------------------------------------------------------------------
__global__ void k_split(const float* __restrict__ src,
                        __half* __restrict__ hi, __half* __restrict__ lo, int n4) {
    int i = blockIdx.x * blockDim.x + threadIdx.x;
    if (i >= n4) return;
    float4 v = ((const float4*)src)[i];
    float vs[4] = {v.x, v.y, v.z, v.w};
    split4_store(vs, hi, lo, i);
}

__global__ void k_splitW(const float* __restrict__ srcA, int n4a,
                         const float* __restrict__ srcB, int n4b,
                         __half* __restrict__ hi) {
    int i = blockIdx.x * blockDim.x + threadIdx.x;
    if (i >= n4a + n4b) return;
    float4 v = (i < n4a) ? ((const float4*)srcA)[i]
                         : ((const float4*)srcB)[i - n4a];
    unsigned short h0, h1, h2, h3, dummy;
    split1(v.x, h0, dummy); split1(v.y, h1, dummy);
    split1(v.z, h2, dummy); split1(v.w, h3, dummy);
    uint2 ph;
    ph.x = (uint32_t)h0 | ((uint32_t)h1 << 16);
    ph.y = (uint32_t)h2 | ((uint32_t)h3 << 16);
    ((uint2*)hi)[i] = ph;
}

// ---------------------------------------------------------------------------
// Edge preprocessing
// ---------------------------------------------------------------------------
__global__ void k_zerodet(const void* ei) {
    int i = blockIdx.x * blockDim.x + threadIdx.x;
    for (int j = i; j < NN; j += gridDim.x * blockDim.x) { g_bcnt[j] = 0; g_bcur[j] = 0; }
    if (i == 0) {
        g_mm[0] = 0xFFFFFFFFu; g_mm[1] = 0u;
        const int* p = (const int*)ei;
        int nz = 0;
        for (int k = 1; k < 2001; k += 2) nz |= p[k];
        g_is64 = (nz == 0) ? 1 : 0;
    }
}
__global__ void k_hist(const void* __restrict__ ei, const float* __restrict__ ew) {
    __shared__ unsigned smn, smx;
    if (threadIdx.x == 0) { smn = 0xFFFFFFFFu; smx = 0u; }
    __syncthreads();
    unsigned mn = 0xFFFFFFFFu, mx = 0u;
    for (int e = blockIdx.x * blockDim.x + threadIdx.x; e < EE; e += gridDim.x * blockDim.x) {
        unsigned b = __float_as_uint(ew[e]);
        mn = min(mn, b); mx = max(mx, b);
        atomicAdd(&g_bcnt[load_idx(ei, (size_t)EE + e)], 1);
    }
    #pragma unroll
    for (int o = 16; o; o >>= 1) {
        mn = min(mn, __shfl_xor_sync(0xFFFFFFFFu, mn, o));
        mx = max(mx, __shfl_xor_sync(0xFFFFFFFFu, mx, o));
    }
    if ((threadIdx.x & 31) == 0) { atomicMin(&smn, mn); atomicMax(&smx, mx); }
    __syncthreads();
    if (threadIdx.x == 0) { atomicMin(&g_mm[0], smn); atomicMax(&g_mm[1], smx); }
}
// Warp-shuffle two-level block scan (replaces 20-sync naive scan).
__global__ void k_scan1() {
    __shared__ int wsum[32];
    int i = blockIdx.x * 1024 + threadIdx.x;
    int v = (i < NN) ? g_bcnt[i] : 0;
    int lane = threadIdx.x & 31, wd = threadIdx.x >> 5;
    int s = v;
    #pragma unroll
    for (int o = 1; o < 32; o <<= 1) {
        int t = __shfl_up_sync(0xFFFFFFFFu, s, o);
        if (lane >= o) s += t;
    }
    if (lane == 31) wsum[wd] = s;
    __syncthreads();
    if (wd == 0) {
        int ws = wsum[lane];
        #pragma unroll
        for (int o = 1; o < 32; o <<= 1) {
            int t = __shfl_up_sync(0xFFFFFFFFu, ws, o);
            if (lane >= o) ws += t;
        }
        wsum[lane] = ws;
    }
    __syncthreads();
    int off = wd ? wsum[wd - 1] : 0;
    if (i < NN) g_boff[i] = off + s - v;
    if (threadIdx.x == 1023) g_part[blockIdx.x] = off + s;
}
__global__ void k_scan2() {
    __shared__ int s[64];
    int v = (threadIdx.x < NB1) ? g_part[threadIdx.x] : 0;
    s[threadIdx.x] = v;
    __syncthreads();
    for (int o = 1; o < 64; o <<= 1) {
        int t = (threadIdx.x >= o) ? s[threadIdx.x - o] : 0;
        __syncthreads();
        s[threadIdx.x] += t;
        __syncthreads();
    }
    if (threadIdx.x < NB1) g_part[threadIdx.x] = s[threadIdx.x] - v;
}
__global__ void k_scan3() {
    int i = blockIdx.x * blockDim.x + threadIdx.x;
    for (int j = i; j < NN; j += gridDim.x * blockDim.x)
        g_boff[j] += g_part[j >> 10];
    if (i == 0) g_boff[NN] = EE;
}
__global__ void k_reorder(const void* __restrict__ ei, const float* __restrict__ ew,
                          const void* __restrict__ et) {
    float mn = __uint_as_float(g_mm[0]);
    float mx = __uint_as_float(g_mm[1]);
    float sc = 1.0f / (mx - mn + 1e-8f);
    for (int e = blockIdx.x * blockDim.x + threadIdx.x; e < EE; e += gridDim.x * blockDim.x) {
        int src = load_idx(ei, e);
        int dst = load_idx(ei, (size_t)EE + e);
        int r   = load_idx(et, e);
        int cnt = g_boff[dst + 1] - g_boff[dst];
        int pos = g_boff[dst] + atomicAdd(&g_bcur[dst], 1);
        float coef = (ew[e] - mn) * sc / (float)max(cnt, 1);
        g_emeta[pos] = make_int2(src * RR + r, __float_as_int(coef));
    }
}

// ---------------------------------------------------------------------------
// mma.sync fp16 2-term GEMM, full-slot width per CTA.
// Epilogue: acc staged in smem (overlaying the A region), then written with
// fully-coalesced 16B-per-lane row stores.
// Slots 0..7 -> fp16 Yh (layout Yh[n][r][c], row stride RR*BNT halves);
// slot 8 -> fp32 R (row stride BNT floats).
// ---------------------------------------------------------------------------
#define PKA 136   // A smem row halves: 272B stride
#define SM_APL (128 * PKA * 2)          // 34816 per plane

template <int BNT>
__global__ void __launch_bounds__(256, 2)
tc_gemm(const __half* __restrict__ Ah, const __half* __restrict__ Al,
        const __half* __restrict__ Bh0, long strideB,
        __half* __restrict__ Yh, float* __restrict__ R) {
    constexpr int PNB = BNT + 8;
    constexpr int SBB = PNB * 2;
    constexpr int NP = BNT / 16;
    constexpr int CH = BNT / 8;
    constexpr int PC = BNT + 8;          // staging row stride (halves / floats)

    extern __shared__ char smem[];
    int tid = threadIdx.x, wid = tid >> 5, lane = tid & 31;
    int row0 = blockIdx.x * 128;
    const __half* Bh = Bh0 + (size_t)blockIdx.y * strideB;

    uint32_t uAh = smem_u32(smem);
    uint32_t uAl = uAh + SM_APL;
    uint32_t uBh = uAh + 2 * SM_APL;

    #pragma unroll
    for (int i = 0; i < 8; i++) {
        int c = tid + i * 256;
        int row = c >> 4, col = c & 15;
        int gr = row0 + row;
        uint32_t ok = (gr < NN) ? 16u : 0u;
        int grc = gr < NN ? gr : NN - 1;
        cp16(uAh + row * 272 + col * 16,
             (const char*)(Ah + (size_t)grc * FF) + col * 16, ok);
        cp16(uAl + row * 272 + col * 16,
             (const char*)(Al + (size_t)grc * FF) + col * 16, ok);
    }
    #pragma unroll
    for (int i = 0; i < CH / 2; i++) {
        int c = tid + i * 256;
        int row = c / CH, col = c % CH;
        cp16(uBh + row * SBB + col * 16,
             (const char*)(Bh + (size_t)row * BNT) + col * 16, 16u);
    }
    asm volatile("cp.async.commit_group;" ::: "memory");
    asm volatile("cp.async.wait_group 0;" ::: "memory");
    __syncthreads();

    float acc[2 * NP][4];
    #pragma unroll
    for (int i = 0; i < 2 * NP; i++)
        #pragma unroll
        for (int q = 0; q < 4; q++) acc[i][q] = 0.f;

    int r = lane & 7, j = lane >> 3;
    int amrow = wid * 16 + r + 8 * (j & 1);
    int bncol0 = 8 * (j >> 1);

    #pragma unroll
    for (int ks = 0; ks < 8; ks++) {
        int k0 = ks * 16;
        uint32_t ah[4], al[4];
        int akcol = k0 + 8 * (j >> 1);
        ldsm_x4(ah[0], ah[1], ah[2], ah[3], uAh + (amrow * PKA + akcol) * 2);
        ldsm_x4(al[0], al[1], al[2], al[3], uAl + (amrow * PKA + akcol) * 2);
        int bkrow = k0 + r + 8 * (j & 1);
        #pragma unroll
        for (int p = 0; p < NP; p++) {
            uint32_t b0, b1, b2, b3;
            ldsm_x4t(b0, b1, b2, b3, uBh + bkrow * SBB + (p * 16 + bncol0) * 2);
            mma_f16(acc[2 * p + 0], ah, b0, b1);
            mma_f16(acc[2 * p + 0], al, b0, b1);
            mma_f16(acc[2 * p + 1], ah, b2, b3);
            mma_f16(acc[2 * p + 1], al, b2, b3);
        }
    }

    // ---- staged, coalesced epilogue (A region reused as C staging) ----
    __syncthreads();
    int lr = wid * 16 + lane / 4;
    int oc0 = 2 * (lane & 3);
    if (blockIdx.y < RR) {
        __half* sC = (__half*)smem;             // [128][PC] halves
        #pragma unroll
        for (int nt = 0; nt < 2 * NP; nt++) {
            int col = nt * 8 + oc0;
            *(__half2*)&sC[lr * PC + col] =
                __floats2half2_rn(acc[nt][0], acc[nt][1]);
            *(__half2*)&sC[(lr + 8) * PC + col] =
                __floats2half2_rn(acc[nt][2], acc[nt][3]);
        }
        __syncthreads();
        __half* base = Yh + (size_t)blockIdx.y * BNT;
        constexpr int CHR = BNT * 2 / 16;       // 16B chunks per row
        #pragma unroll
        for (int i = 0; i < (128 * CHR) / 256; i++) {
            int c = tid + i * 256;
            int row = c / CHR, col = c % CHR;
            int gr = row0 + row;
            if (gr < NN) {
                uint4 v = *(uint4*)&sC[row * PC + col * 8];
                *(uint4*)&base[(size_t)gr * (RR * BNT) + col * 8] = v;
            }
        }
    } else {
        float* sCf = (float*)smem;              // [128][PC] floats
        #pragma unroll
        for (int nt = 0; nt < 2 * NP; nt++) {
            int col = nt * 8 + oc0;
            *(float2*)&sCf[lr * PC + col] = make_float2(acc[nt][0], acc[nt][1]);
            *(float2*)&sCf[(lr + 8) * PC + col] = make_float2(acc[nt][2], acc[nt][3]);
        }
        __syncthreads();
        constexpr int CHRF = BNT * 4 / 16;      // 16B chunks per row
        #pragma unroll
        for (int i = 0; i < (128 * CHRF) / 256; i++) {
            int c = tid + i * 256;
            int row = c / CHRF, col = c % CHRF;
            int gr = row0 + row;
            if (gr < NN) {
                uint4 v = *(uint4*)&sCf[row * PC + col * 4];
                *(uint4*)&R[(size_t)gr * BNT + col * 4] = v;
            }
        }
    }
}

// ---------------------------------------------------------------------------
// Layer-1 aggregate, MLP-8, fp16 message gather.
// ---------------------------------------------------------------------------
__global__ void k_agg1(const __half* __restrict__ Yh, const float* __restrict__ R,
                       const float* __restrict__ bias,
                       __half* __restrict__ hh, __half* __restrict__ hl) {
    int w = (blockIdx.x * blockDim.x + threadIdx.x) >> 5;
    int lane = threadIdx.x & 31;
    if (w >= NN) return;
    int s0 = g_boff[w], s1 = g_boff[w + 1];

    float4 rv = *(const float4*)(R + (size_t)w * HH + lane * 4);
    float4 bv = *(const float4*)(bias + lane * 4);
    float a0 = rv.x + bv.x, a1 = rv.y + bv.y, a2 = rv.z + bv.z, a3 = rv.w + bv.w;

    for (int base = s0; base < s1; base += 32) {
        int idx = base + lane;
        int2 m = (idx < s1) ? g_emeta[idx] : make_int2(0, 0);
        int cnt = min(32, s1 - base);
        for (int jj = 0; jj < cnt; jj += 8) {
            int sr[8]; float cf[8];
            #pragma unroll
            for (int q = 0; q < 8; q++) {
                sr[q] = __shfl_sync(0xFFFFFFFFu, m.x, jj + q);
                cf[q] = __int_as_float(__shfl_sync(0xFFFFFFFFu, m.y, jj + q));
            }
            uint2 raw[8];
            #pragma unroll
            for (int q = 0; q < 8; q++)
                raw[q] = *(const uint2*)(Yh + (size_t)sr[q] * HH + lane * 4);
            #pragma unroll
            for (int q = 0; q < 8; q++) {
                float2 f0 = __half22float2(*(__half2*)&raw[q].x);
                float2 f1 = __half22float2(*(__half2*)&raw[q].y);
                a0 += cf[q] * f0.x; a1 += cf[q] * f0.y;
                a2 += cf[q] * f1.x; a3 += cf[q] * f1.y;
            }
        }
    }
    float vs[4] = {fmaxf(a0, 0.f), fmaxf(a1, 0.f), fmaxf(a2, 0.f), fmaxf(a3, 0.f)};
    split4_store(vs, hh + (size_t)w * FF, hl + (size_t)w * FF, lane);
}

// ---------------------------------------------------------------------------
// Layer-2 aggregate, MLP-8, fp16 message gather: out = R + bias + msgs.
// ---------------------------------------------------------------------------
__global__ void k_agg2(const __half* __restrict__ Yh, const float* __restrict__ R,
                       const float* __restrict__ bias, float* __restrict__ out) {
    int w = (blockIdx.x * blockDim.x + threadIdx.x) >> 5;
    int lane = threadIdx.x & 31;
    if (w >= NN) return;
    int s0 = g_boff[w], s1 = g_boff[w + 1];

    float2 rv = *(const float2*)(R + (size_t)w * OO + lane * 2);
    float a0 = rv.x + bias[lane * 2], a1 = rv.y + bias[lane * 2 + 1];

    for (int base = s0; base < s1; base += 32) {
        int idx = base + lane;
        int2 m = (idx < s1) ? g_emeta[idx] : make_int2(0, 0);
        int cnt = min(32, s1 - base);
        for (int jj = 0; jj < cnt; jj += 8) {
            int sr[8]; float cf[8];
            #pragma unroll
            for (int q = 0; q < 8; q++) {
                sr[q] = __shfl_sync(0xFFFFFFFFu, m.x, jj + q);
                cf[q] = __int_as_float(__shfl_sync(0xFFFFFFFFu, m.y, jj + q));
            }
            uint32_t raw[8];
            #pragma unroll
            for (int q = 0; q < 8; q++)
                raw[q] = *(const uint32_t*)(Yh + (size_t)sr[q] * OO + lane * 2);
            #pragma unroll
            for (int q = 0; q < 8; q++) {
                float2 f0 = __half22float2(*(__half2*)&raw[q]);
                a0 += cf[q] * f0.x; a1 += cf[q] * f0.y;
            }
        }
    }
    *(float2*)&out[(size_t)w * OO + lane * 2] = make_float2(a0, a1);
}

// ---------------------------------------------------------------------------
// Launch
// ---------------------------------------------------------------------------
extern "C" void kernel_launch(void* const* d_in, const int* in_sizes, int n_in,
                              void* d_out, int out_size) {
    const float* x     = (const float*)d_in[0];
    const void*  ei    = d_in[1];
    const float* ew    = (const float*)d_in[2];
    const void*  et    = d_in[3];
    const float* W1    = (const float*)d_in[4];
    const float* root1 = (const float*)d_in[5];
    const float* bias1 = (const float*)d_in[6];
    const float* W2    = (const float*)d_in[7];
    const float* root2 = (const float*)d_in[8];
    const float* bias2 = (const float*)d_in[9];
    float* out = (float*)d_out;

    void *pYh, *pR, *pAh, *pAl, *pWh;
    cudaGetSymbolAddress(&pYh, g_Yh);
    cudaGetSymbolAddress(&pR, g_R);
    cudaGetSymbolAddress(&pAh, g_Ah);
    cudaGetSymbolAddress(&pAl, g_Al);
    cudaGetSymbolAddress(&pWh, g_Wh);
    __half* Yh = (__half*)pYh;
    float*  Rp = (float*)pR;
    __half* Ah = (__half*)pAh;
    __half* Al = (__half*)pAl;
    __half* Wh = (__half*)pWh;

    const int GB = (NN + 127) / 128;   // 391 row tiles
    const int GA = (NN * 32 + 255) / 256;
    const int SMEM128 = 2 * SM_APL + 128 * (128 + 8) * 2;  // 104448
    const int SMEM64  = 2 * SM_APL + 128 * (64 + 8) * 2;   // 88064
    cudaFuncSetAttribute(tc_gemm<128>, cudaFuncAttributeMaxDynamicSharedMemorySize, SMEM128);
    cudaFuncSetAttribute(tc_gemm<64>,  cudaFuncAttributeMaxDynamicSharedMemorySize, SMEM64);

    k_zerodet<<<256, 256>>>(ei);                                     // 1
    k_split<<<(NN * FF / 4 + 255) / 256, 256>>>(x, Ah, Al, NN * FF / 4);          // 2
    k_splitW<<<((RR * FF * HH + FF * HH) / 4 + 255) / 256, 256>>>(   // 3
        W1, RR * FF * HH / 4, root1, FF * HH / 4, Wh);
    // Y1 (slots 0..7 fp16 msgs, slot 8 fp32 root): grid (391, 9)
    tc_gemm<128><<<dim3(GB, NS), 256, SMEM128>>>(                    // 4 (profiled)
        Ah, Al, Wh, (long)FF * HH, Yh, Rp);

    k_hist<<<1024, 256>>>(ei, ew);                                   // 5
    k_scan1<<<NB1, 1024>>>();                                        // 6
    k_scan2<<<1, 64>>>();                                            // 7
    k_scan3<<<256, 256>>>();                                         // 8
    k_reorder<<<1024, 256>>>(ei, ew, et);                            // 9

    // h = relu(root + bias1 + agg) -> fp16 planes
    k_agg1<<<GA, 256>>>(Yh, Rp, bias1, Ah, Al);                      // 10

    k_splitW<<<((RR * HH * OO + HH * OO) / 4 + 255) / 256, 256>>>(   // 11
        W2, RR * HH * OO / 4, root2, HH * OO / 4, Wh);
    // Y2: grid (391, 9), BN=64
    tc_gemm<64><<<dim3(GB, NS), 256, SMEM64>>>(                      // 12
        Ah, Al, Wh, (long)HH * OO, Yh, Rp);

    // out = root + bias2 + agg
    k_agg2<<<GA, 256>>>(Yh, Rp, bias2, out);                         // 13
}